// round 10
// baseline (speedup 1.0000x reference)
#include <cuda_runtime.h>
#include <cstdint>
#include <cstddef>
#include <math.h>

#define S    4096
#define L    16
#define H    512
#define EC   128
#define EW   512
#define HH   256
#define G4H  2048   // 4*H
#define G4HH 1024   // 4*HH
#define NPOS 64
#define NNER 32
#define KCAT 640    // EC + H

typedef unsigned long long ull;

// ---------------- scratch (device globals; no dynamic allocation) ----------------
__device__ float g_Xc[(size_t)L * S * EC];     // [t][slot][e]  char embeddings, sorted order
__device__ float g_hA[(size_t)S * H];          // char LSTM hidden ping
__device__ float g_hB[(size_t)S * H];          // char LSTM hidden pong
__device__ float g_c [(size_t)S * H];          // char LSTM cell (sorted order)
__device__ float g_wc [(size_t)S * (EW + H)];  // word LSTM input [S,1024] (orig order)
__device__ float g_xgf[(size_t)S * G4HH];      // precomputed x-gates fwd
__device__ float g_xgb[(size_t)S * G4HH];      // precomputed x-gates bwd
__device__ float g_out[(size_t)S * H];         // bi-LSTM output [S,512]
__device__ float g_Wcat[(size_t)G4H * KCAT];   // permuted concat(Wih_c|Whh_c), gate-interleaved
__device__ float g_biasP[G4H];                 // permuted bih_c+bhh_c
__device__ int   g_perm[S];                    // sorted slot -> original index
__device__ int   g_inv[S];                     // original index -> sorted slot
__device__ int   g_lensS[S];                   // lens in sorted order (descending)
__device__ int   g_cnt[L];                     // cnt[t] = #words with len > t

// fast transcendentals (err ~1e-7 rel; tolerance is 1e-3)
__device__ __forceinline__ float fsig(float x) {
    return __fdividef(1.f, 1.f + __expf(-x));
}
__device__ __forceinline__ float ftanh(float x) {
    return 1.f - __fdividef(2.f, __expf(2.f * x) + 1.f);
}

__device__ __forceinline__ ull pack2(float x, float y) {
    ull r; asm("mov.b64 %0,{%1,%2};" : "=l"(r) : "f"(x), "f"(y)); return r;
}
__device__ __forceinline__ void unpack2(ull v, float& x, float& y) {
    asm("mov.b64 {%0,%1},%2;" : "=f"(x), "=f"(y) : "l"(v));
}
__device__ __forceinline__ ull ffma2(ull a, ull b, ull c) {
    ull d; asm("fma.rn.f32x2 %0,%1,%2,%3;" : "=l"(d) : "l"(a), "l"(b), "l"(c)); return d;
}

// ---------------- counting sort by char length (descending) ----------------
__global__ void k_sort(const int* __restrict__ lens) {
    __shared__ int hist[17], off[17];
    int tid = threadIdx.x;
    if (tid < 17) hist[tid] = 0;
    __syncthreads();
    for (int s = tid; s < S; s += blockDim.x) atomicAdd(&hist[lens[s]], 1);
    __syncthreads();
    if (tid == 0) {
        int acc = 0;
        for (int l = 16; l >= 1; --l) { off[l] = acc; acc += hist[l]; }
        for (int t = 0; t < L; ++t) g_cnt[t] = off[t + 1] + hist[t + 1];
    }
    __syncthreads();
    for (int s = tid; s < S; s += blockDim.x) {
        int l = lens[s];
        int pos = atomicAdd(&off[l], 1);
        g_perm[pos] = s;
        g_inv[s] = pos;
        g_lensS[pos] = l;
    }
}

// ---------------- fused prep: permuted weights + bias + h/c init -----------------
__global__ void k_prep_all(const float* __restrict__ Wih_c,
                           const float* __restrict__ Whh_c,
                           const float* __restrict__ bih_c,
                           const float* __restrict__ bhh_c,
                           const int*   __restrict__ feat_seq,
                           const float* __restrict__ prefix_emb) {
    int b = blockIdx.x;
    if (b < 5120) {
        int idx = b * 256 + threadIdx.x;               // < 2048*640
        int n = idx / KCAT, k = idx % KCAT;
        int jh = n >> 2, g = n & 3;
        int row = g * H + jh;
        g_Wcat[idx] = (k < EC) ? Wih_c[(size_t)row * EC + k]
                               : Whh_c[(size_t)row * H + (k - EC)];
    } else if (b < 5128) {
        int n = (b - 5120) * 256 + threadIdx.x;        // < 2048
        int jh = n >> 2, g = n & 3;
        int row = g * H + jh;
        g_biasP[n] = bih_c[row] + bhh_c[row];
    } else {
        int idx = (b - 5128) * 256 + threadIdx.x;      // < S*128 (float4 units)
        int j4 = idx & 127;
        int slot = idx >> 7;
        int s = g_perm[slot];
        reinterpret_cast<float4*>(g_hA)[idx] =
            reinterpret_cast<const float4*>(prefix_emb)[(size_t)feat_seq[s] * 128 + j4];
        reinterpret_cast<float4*>(g_c)[idx] = make_float4(0.f, 0.f, 0.f, 0.f);
    }
}

// ---------------- embedding gather (sorted order, float4) ----------------
__global__ void k_gather_xc(const int* __restrict__ chars,
                            const float* __restrict__ char_emb) {
    int idx = blockIdx.x * blockDim.x + threadIdx.x;   // < L*S*32
    int e4 = idx & 31;
    int slot = (idx >> 5) & (S - 1);
    int t = idx >> 17;
    int s = g_perm[slot];
    reinterpret_cast<float4*>(g_Xc)[idx] =
        reinterpret_cast<const float4*>(char_emb)[(size_t)chars[s * L + t] * 32 + e4];
}

__global__ void k_build_wc(const int* __restrict__ word_seq,
                           const float* __restrict__ word_emb) {
    int idx = blockIdx.x * blockDim.x + threadIdx.x;   // < S*256
    int k4 = idx & 255;
    int s = idx >> 8;
    float4 v;
    if (k4 < 128) {
        v = reinterpret_cast<const float4*>(word_emb)[(size_t)word_seq[s] * 128 + k4];
    } else {
        int slot = g_inv[s];
        int len = g_lensS[slot];
        const float4* hp = reinterpret_cast<const float4*>((len & 1) ? g_hB : g_hA);
        v = hp[(size_t)slot * 128 + (k4 - 128)];
    }
    reinterpret_cast<float4*>(g_wc)[idx] = v;
}

// ---------------- fused char-LSTM step: gates GEMM + cell update ----------------
// Block tile 128(M)x256(N), thread tile 8 rows x (8+8) cols, FFMA2,
// double-buffered smem. Halves LDS-per-FLOP vs the 128x128 tile.
__global__ __launch_bounds__(256, 1)
void k_char_step(const float* __restrict__ Xc_t,
                 const float* __restrict__ hcur,
                 float* __restrict__ hnxt, int t) {
    const int cnt = g_cnt[t];
    const int m0 = blockIdx.y * 128;
    if (m0 >= cnt) return;
    const int n0 = blockIdx.x * 256;

    __shared__ __align__(16) float As[2][8][128];
    __shared__ __align__(16) float Bs[2][8][256];

    const int tid = threadIdx.x;
    const int row = tid >> 1;             // 0..127
    const int kc  = (tid & 1) * 4;        // 0 or 4
    const int tx  = tid & 15, ty = tid >> 4;

    ull acc2[8][8];
    #pragma unroll
    for (int i = 0; i < 8; i++)
        #pragma unroll
        for (int j = 0; j < 8; j++) acc2[i][j] = 0ULL;

    float4 pA, pB0, pB1;
    auto loadT = [&](int kt) {
        int k = kt + kc;
        const float* srcA = (k < EC)
            ? (Xc_t + (size_t)(m0 + row) * EC + k)
            : (hcur + (size_t)(m0 + row) * H + (k - EC));
        pA  = *reinterpret_cast<const float4*>(srcA);
        pB0 = *reinterpret_cast<const float4*>(g_Wcat + (size_t)(n0 + row) * KCAT + k);
        pB1 = *reinterpret_cast<const float4*>(g_Wcat + (size_t)(n0 + row + 128) * KCAT + k);
    };
    auto stsT = [&](int buf) {
        As[buf][kc + 0][row] = pA.x;  As[buf][kc + 1][row] = pA.y;
        As[buf][kc + 2][row] = pA.z;  As[buf][kc + 3][row] = pA.w;
        Bs[buf][kc + 0][row] = pB0.x; Bs[buf][kc + 1][row] = pB0.y;
        Bs[buf][kc + 2][row] = pB0.z; Bs[buf][kc + 3][row] = pB0.w;
        Bs[buf][kc + 0][row + 128] = pB1.x; Bs[buf][kc + 1][row + 128] = pB1.y;
        Bs[buf][kc + 2][row + 128] = pB1.z; Bs[buf][kc + 3][row + 128] = pB1.w;
    };

    loadT(0);
    stsT(0);
    __syncthreads();

    int cur = 0;
    for (int kt = 0; kt < KCAT; kt += 8) {
        bool more = (kt + 8) < KCAT;
        if (more) loadT(kt + 8);
        #pragma unroll
        for (int kk = 0; kk < 8; kk++) {
            float a[8];
            *reinterpret_cast<float4*>(&a[0]) = *reinterpret_cast<const float4*>(&As[cur][kk][ty * 8]);
            *reinterpret_cast<float4*>(&a[4]) = *reinterpret_cast<const float4*>(&As[cur][kk][ty * 8 + 4]);
            ull b2[8];
            {
                const ull* bp0 = reinterpret_cast<const ull*>(&Bs[cur][kk][tx * 8]);
                const ull* bp1 = reinterpret_cast<const ull*>(&Bs[cur][kk][128 + tx * 8]);
                b2[0] = bp0[0]; b2[1] = bp0[1]; b2[2] = bp0[2]; b2[3] = bp0[3];
                b2[4] = bp1[0]; b2[5] = bp1[1]; b2[6] = bp1[2]; b2[7] = bp1[3];
            }
            #pragma unroll
            for (int i = 0; i < 8; i++) {
                ull ad = pack2(a[i], a[i]);
                #pragma unroll
                for (int j = 0; j < 8; j++)
                    acc2[i][j] = ffma2(ad, b2[j], acc2[i][j]);
            }
        }
        if (more) {
            stsT(cur ^ 1);
            __syncthreads();
            cur ^= 1;
        }
    }

    // epilogue: bias + LSTM cell for 4 hidden units x 8 rows per thread
    float bn0[8], bn1[8];
    #pragma unroll
    for (int j = 0; j < 8; j++) {
        bn0[j] = g_biasP[n0 + tx * 8 + j];
        bn1[j] = g_biasP[n0 + 128 + tx * 8 + j];
    }
    const int u0 = (n0 >> 2) + tx * 2;        // chunk0: units u0, u0+1
    const int u1 = u0 + 32;                   // chunk1: units u1, u1+1

    #pragma unroll
    for (int i = 0; i < 8; i++) {
        int m = m0 + ty * 8 + i;
        if (t < g_lensS[m]) {
            float v[16];
            #pragma unroll
            for (int j = 0; j < 8; j++) unpack2(acc2[i][j], v[2 * j], v[2 * j + 1]);
            size_t c0 = (size_t)m * H + u0;
            size_t c1 = (size_t)m * H + u1;
            #pragma unroll
            for (int u = 0; u < 2; u++) {
                float iv = v[4 * u + 0] + bn0[4 * u + 0];
                float fv = v[4 * u + 1] + bn0[4 * u + 1];
                float gv = v[4 * u + 2] + bn0[4 * u + 2];
                float ov = v[4 * u + 3] + bn0[4 * u + 3];
                float c = g_c[c0 + u];
                c = fsig(fv) * c + fsig(iv) * ftanh(gv);
                g_c[c0 + u] = c;
                hnxt[c0 + u] = fsig(ov) * ftanh(c);
            }
            #pragma unroll
            for (int u = 0; u < 2; u++) {
                float iv = v[8 + 4 * u + 0] + bn1[4 * u + 0];
                float fv = v[8 + 4 * u + 1] + bn1[4 * u + 1];
                float gv = v[8 + 4 * u + 2] + bn1[4 * u + 2];
                float ov = v[8 + 4 * u + 3] + bn1[4 * u + 3];
                float c = g_c[c1 + u];
                c = fsig(fv) * c + fsig(iv) * ftanh(gv);
                g_c[c1 + u] = c;
                hnxt[c1 + u] = fsig(ov) * ftanh(c);
            }
        }
    }
}

// ---------------- merged x-gate GEMM (fwd + bwd via blockIdx.z) ----------------
__global__ __launch_bounds__(256)
void gemm_xg(const float* __restrict__ A1,
             const float* __restrict__ Bf, const float* __restrict__ Bb,
             const float* __restrict__ b1f, const float* __restrict__ b2f,
             const float* __restrict__ b1b, const float* __restrict__ b2b,
             float* __restrict__ Cf, float* __restrict__ Cb) {
    const int K1 = EW + H, N = G4HH;
    const int BM = 128, BN = 128, BK = 8;
    const float* B1 = blockIdx.z ? Bb : Bf;
    const float* b1 = blockIdx.z ? b1b : b1f;
    const float* b2 = blockIdx.z ? b2b : b2f;
    float* C = blockIdx.z ? Cb : Cf;

    __shared__ __align__(16) float As[BK][BM];
    __shared__ __align__(16) float Bs[BK][BN];
    int tid = threadIdx.x;
    int m0 = blockIdx.y * BM;
    int n0 = blockIdx.x * BN;
    int aRow = tid >> 1, aCol = (tid & 1) * 4;
    int tx = tid & 15, ty = tid >> 4;

    ull acc2[8][4];
    #pragma unroll
    for (int i = 0; i < 8; i++)
        #pragma unroll
        for (int j = 0; j < 4; j++) acc2[i][j] = 0ULL;

    for (int kt = 0; kt < K1; kt += BK) {
        int k = kt + aCol;
        {
            float4 v = *reinterpret_cast<const float4*>(A1 + (size_t)(m0 + aRow) * K1 + k);
            As[aCol + 0][aRow] = v.x; As[aCol + 1][aRow] = v.y;
            As[aCol + 2][aRow] = v.z; As[aCol + 3][aRow] = v.w;
        }
        {
            float4 v = *reinterpret_cast<const float4*>(B1 + (size_t)(n0 + aRow) * K1 + k);
            Bs[aCol + 0][aRow] = v.x; Bs[aCol + 1][aRow] = v.y;
            Bs[aCol + 2][aRow] = v.z; Bs[aCol + 3][aRow] = v.w;
        }
        __syncthreads();
        #pragma unroll
        for (int kk = 0; kk < BK; kk++) {
            float a[8];
            *reinterpret_cast<float4*>(&a[0]) = *reinterpret_cast<const float4*>(&As[kk][ty * 8]);
            *reinterpret_cast<float4*>(&a[4]) = *reinterpret_cast<const float4*>(&As[kk][ty * 8 + 4]);
            ull b2r[4];
            const ull* bp = reinterpret_cast<const ull*>(&Bs[kk][tx * 8]);
            b2r[0] = bp[0]; b2r[1] = bp[1]; b2r[2] = bp[2]; b2r[3] = bp[3];
            #pragma unroll
            for (int i = 0; i < 8; i++) {
                ull ad = pack2(a[i], a[i]);
                #pragma unroll
                for (int j = 0; j < 4; j++)
                    acc2[i][j] = ffma2(ad, b2r[j], acc2[i][j]);
            }
        }
        __syncthreads();
    }
    #pragma unroll
    for (int i = 0; i < 8; i++) {
        int m = m0 + ty * 8 + i;
        #pragma unroll
        for (int jj = 0; jj < 4; jj++) {
            float lo, hi;
            unpack2(acc2[i][jj], lo, hi);
            int n = n0 + tx * 8 + jj * 2;
            C[(size_t)m * N + n]     = lo + b1[n] + b2[n];
            C[(size_t)m * N + n + 1] = hi + b1[n + 1] + b2[n + 1];
        }
    }
}

// ---------------- word bi-LSTM recurrence: 2 clusters of 8 CTAs, 512 thr ----------
// R9 proven version (two-stage step, warp-0 tail, cluster barrier).
__global__ void __cluster_dims__(8, 1, 1) __launch_bounds__(512, 1)
k_word_lstm(const float* __restrict__ Whh_f, const float* __restrict__ Whh_b) {
    __shared__ __align__(16) float hb[2][HH];
    __shared__ float partial[512];

    unsigned rank;
    asm("mov.u32 %0, %%cluster_ctarank;" : "=r"(rank));
    int dir = blockIdx.x / 8;                   // 0 = fwd, 1 = bwd
    const float* Whh = dir ? Whh_b : Whh_f;
    const float* xg  = dir ? g_xgb : g_xgf;

    int tid = threadIdx.x;
    int p   = tid & 127;       // gate-row within CTA: gate*32 + jj
    int q   = tid >> 7;        // k-quarter (0..3)
    int gte = p >> 5;
    int jj  = p & 31;
    int grow = gte * HH + (int)rank * 32 + jj;  // row in Whh[1024][256]

    ull w2[32];
    const float4* wsrc = reinterpret_cast<const float4*>(Whh + (size_t)grow * HH + q * 64);
    #pragma unroll
    for (int i = 0; i < 16; i++) {
        float4 f = wsrc[i];
        w2[2 * i]     = pack2(f.x, f.y);
        w2[2 * i + 1] = pack2(f.z, f.w);
    }

    int lane = tid & 31;
    unsigned raA[8], raB[8];
    {
        unsigned loff0 = (unsigned)__cvta_generic_to_shared(&hb[0][rank * 32 + lane]);
        unsigned loff1 = (unsigned)__cvta_generic_to_shared(&hb[1][rank * 32 + lane]);
        #pragma unroll
        for (int peer = 0; peer < 8; ++peer) {
            asm("mapa.shared::cluster.u32 %0, %1, %2;" : "=r"(raA[peer]) : "r"(loff0), "r"(peer));
            asm("mapa.shared::cluster.u32 %0, %1, %2;" : "=r"(raB[peer]) : "r"(loff1), "r"(peer));
        }
    }

    if (tid < HH) hb[0][tid] = 0.f;
    __syncthreads();
    asm volatile("barrier.cluster.arrive.aligned;" ::: "memory");
    asm volatile("barrier.cluster.wait.aligned;"   ::: "memory");

    float c_reg = 0.f;
    int par = 0;
    const int xbase = (int)rank * 32 + lane;   // x-gate column base (warp-0 lanes)
    float xv0 = 0.f, xv1 = 0.f, xv2 = 0.f, xv3 = 0.f;
    if (tid < 32) {
        size_t r0 = (size_t)(dir ? (S - 1) : 0) * G4HH + xbase;
        xv0 = __ldg(&xg[r0]);       xv1 = __ldg(&xg[r0 + 256]);
        xv2 = __ldg(&xg[r0 + 512]); xv3 = __ldg(&xg[r0 + 768]);
    }

    for (int t = 0; t < S; ++t) {
        int row = dir ? (S - 1 - t) : t;

        const ull* hv = reinterpret_cast<const ull*>(&hb[par][q * 64]);
        ull a0 = 0ULL, a1 = 0ULL, a2 = 0ULL, a3 = 0ULL;
        #pragma unroll
        for (int i = 0; i < 32; i += 4) {
            a0 = ffma2(w2[i + 0], hv[i + 0], a0);
            a1 = ffma2(w2[i + 1], hv[i + 1], a1);
            a2 = ffma2(w2[i + 2], hv[i + 2], a2);
            a3 = ffma2(w2[i + 3], hv[i + 3], a3);
        }
        float l0, h0f, l1, h1f, l2, h2f, l3, h3f;
        unpack2(a0, l0, h0f); unpack2(a1, l1, h1f);
        unpack2(a2, l2, h2f); unpack2(a3, l3, h3f);
        partial[tid] = ((l0 + h0f) + (l1 + h1f)) + ((l2 + h2f) + (l3 + h3f));

        float nx0 = 0.f, nx1 = 0.f, nx2 = 0.f, nx3 = 0.f;
        if (tid < 32 && t + 1 < S) {
            int rn = dir ? (S - 2 - t) : (t + 1);
            size_t rb = (size_t)rn * G4HH + xbase;
            nx0 = __ldg(&xg[rb]);       nx1 = __ldg(&xg[rb + 256]);
            nx2 = __ldg(&xg[rb + 512]); nx3 = __ldg(&xg[rb + 768]);
        }
        __syncthreads();
        if (tid < 32) {
            float p0 = (partial[lane]       + partial[lane + 128])
                     + (partial[lane + 256] + partial[lane + 384]);
            float p1 = (partial[32 + lane]       + partial[32 + lane + 128])
                     + (partial[32 + lane + 256] + partial[32 + lane + 384]);
            float p2 = (partial[64 + lane]       + partial[64 + lane + 128])
                     + (partial[64 + lane + 256] + partial[64 + lane + 384]);
            float p3 = (partial[96 + lane]       + partial[96 + lane + 128])
                     + (partial[96 + lane + 256] + partial[96 + lane + 384]);
            float iv = fsig(p0 + xv0);
            float fv = fsig(p1 + xv1);
            float gg = ftanh(p2 + xv2);
            float ov = fsig(p3 + xv3);
            c_reg = fv * c_reg + iv * gg;
            float hnew = ov * ftanh(c_reg);
            g_out[(size_t)row * H + dir * HH + rank * 32 + lane] = hnew;
            if (par == 0) {
                #pragma unroll
                for (int peer = 0; peer < 8; ++peer)
                    asm volatile("st.shared::cluster.f32 [%0], %1;"
                                 :: "r"(raB[peer]), "f"(hnew) : "memory");
            } else {
                #pragma unroll
                for (int peer = 0; peer < 8; ++peer)
                    asm volatile("st.shared::cluster.f32 [%0], %1;"
                                 :: "r"(raA[peer]), "f"(hnew) : "memory");
            }
        }
        asm volatile("barrier.cluster.arrive.aligned;" ::: "memory");
        asm volatile("barrier.cluster.wait.aligned;"   ::: "memory");
        par ^= 1;
        xv0 = nx0; xv1 = nx1; xv2 = nx2; xv3 = nx3;
    }
}

// ---------------- output heads: logits + log_softmax ----------------
__global__ void k_logits(const float* __restrict__ W,   // [C,512]
                         const float* __restrict__ bias,
                         float* __restrict__ dst, int C) {
    __shared__ float row[H];
    __shared__ float red[64];
    int s = blockIdx.x, tid = threadIdx.x;
    for (int k = tid; k < H; k += blockDim.x) row[k] = g_out[(size_t)s * H + k];
    __syncthreads();
    float acc = bias[tid];
    const float4* w4 = reinterpret_cast<const float4*>(W + (size_t)tid * H);
    const float4* r4 = reinterpret_cast<const float4*>(row);
    #pragma unroll 8
    for (int q = 0; q < H / 4; q++) {
        float4 w = w4[q], r = r4[q];
        acc += w.x * r.x + w.y * r.y + w.z * r.z + w.w * r.w;
    }
    red[tid] = acc;
    __syncthreads();
    for (int off = C >> 1; off; off >>= 1) {
        if (tid < off) red[tid] = fmaxf(red[tid], red[tid + off]);
        __syncthreads();
    }
    float mx = red[0];
    __syncthreads();
    red[tid] = expf(acc - mx);
    __syncthreads();
    for (int off = C >> 1; off; off >>= 1) {
        if (tid < off) red[tid] += red[tid + off];
        __syncthreads();
    }
    float lse = mx + logf(red[0]);
    dst[(size_t)s * C + tid] = acc - lse;
}

// ---------------- launch ----------------
extern "C" void kernel_launch(void* const* d_in, const int* in_sizes, int n_in,
                              void* d_out, int out_size) {
    const int*   word_seq   = (const int*)  d_in[0];
    const int*   chars      = (const int*)  d_in[1];
    const int*   char_lens  = (const int*)  d_in[2];
    const int*   feat_seq   = (const int*)  d_in[3];
    const float* char_emb   = (const float*)d_in[4];
    const float* word_emb   = (const float*)d_in[5];
    const float* prefix_emb = (const float*)d_in[6];
    const float* Wih_c = (const float*)d_in[7];
    const float* Whh_c = (const float*)d_in[8];
    const float* bih_c = (const float*)d_in[9];
    const float* bhh_c = (const float*)d_in[10];
    const float* Wih_f = (const float*)d_in[11];
    const float* Whh_f = (const float*)d_in[12];
    const float* bih_f = (const float*)d_in[13];
    const float* bhh_f = (const float*)d_in[14];
    const float* Wih_b = (const float*)d_in[15];
    const float* Whh_b = (const float*)d_in[16];
    const float* bih_b = (const float*)d_in[17];
    const float* bhh_b = (const float*)d_in[18];
    const float* Wpos  = (const float*)d_in[19];
    const float* bpos  = (const float*)d_in[20];
    const float* Wner  = (const float*)d_in[21];
    const float* bner  = (const float*)d_in[22];
    float* out = (float*)d_out;

    float *p_Xc, *p_hA, *p_hB, *p_wc, *p_xgf, *p_xgb;
    cudaGetSymbolAddress((void**)&p_Xc,  g_Xc);
    cudaGetSymbolAddress((void**)&p_hA,  g_hA);
    cudaGetSymbolAddress((void**)&p_hB,  g_hB);
    cudaGetSymbolAddress((void**)&p_wc,  g_wc);
    cudaGetSymbolAddress((void**)&p_xgf, g_xgf);
    cudaGetSymbolAddress((void**)&p_xgb, g_xgb);

    // launches 1-3: sort, fused prep, gather
    k_sort<<<1, 256>>>(char_lens);
    k_prep_all<<<5120 + 8 + 2048, 256>>>(Wih_c, Whh_c, bih_c, bhh_c,
                                         feat_seq, prefix_emb);
    k_gather_xc<<<(L * S * 32) / 256, 256>>>(chars, char_emb);

    // char LSTM: 16 fused steps (128x256 tile), h ping-pong, early-exit
    dim3 gridC(G4H / 256, S / 128);
    for (int t = 0; t < L; ++t) {
        float* hcur = (t & 1) ? p_hB : p_hA;
        float* hnxt = (t & 1) ? p_hA : p_hB;
        k_char_step<<<gridC, 256>>>(p_Xc + (size_t)t * S * EC, hcur, hnxt, t);
    }

    // word LSTM input + merged x-gate precompute (fwd+bwd in one launch)
    k_build_wc<<<(S * 256) / 256, 256>>>(word_seq, word_emb);
    dim3 gridX(G4HH / 128, S / 128, 2);
    gemm_xg<<<gridX, 256>>>(p_wc, Wih_f, Wih_b,
                            bih_f, bhh_f, bih_b, bhh_b,
                            p_xgf, p_xgb);

    // sequential bi-LSTM recurrence (2 clusters of 8 CTAs, fwd + bwd concurrent)
    k_word_lstm<<<16, 512>>>(Whh_f, Whh_b);

    // output heads
    k_logits<<<S, NPOS>>>(Wpos, bpos, out, NPOS);
    k_logits<<<S, NNER>>>(Wner, bner, out + (size_t)S * NPOS, NNER);

    (void)in_sizes; (void)n_in; (void)out_size;
}

// round 11
// speedup vs baseline: 1.0534x; 1.0534x over previous
#include <cuda_runtime.h>
#include <cstdint>
#include <cstddef>
#include <math.h>

#define S    4096
#define L    16
#define H    512
#define EC   128
#define EW   512
#define HH   256
#define G4H  2048   // 4*H
#define G4HH 1024   // 4*HH
#define NPOS 64
#define NNER 32
#define KCAT 640    // EC + H

typedef unsigned long long ull;

// ---------------- scratch (device globals; no dynamic allocation) ----------------
__device__ float g_Xc[(size_t)L * S * EC];     // [t][slot][e]  char embeddings, sorted order
__device__ float g_hA[(size_t)S * H];          // char LSTM hidden ping
__device__ float g_hB[(size_t)S * H];          // char LSTM hidden pong
__device__ float g_c [(size_t)S * H];          // char LSTM cell (sorted order)
__device__ float g_wc [(size_t)S * (EW + H)];  // word LSTM input [S,1024] (orig order)
__device__ float g_xgf[(size_t)S * G4HH];      // precomputed x-gates fwd
__device__ float g_xgb[(size_t)S * G4HH];      // precomputed x-gates bwd
__device__ float g_out[(size_t)S * H];         // bi-LSTM output [S,512]
__device__ float g_Wcat[(size_t)G4H * KCAT];   // permuted concat(Wih_c|Whh_c), gate-interleaved
__device__ float g_biasP[G4H];                 // permuted bih_c+bhh_c
__device__ int   g_perm[S];                    // sorted slot -> original index
__device__ int   g_inv[S];                     // original index -> sorted slot
__device__ int   g_lensS[S];                   // lens in sorted order (descending)
__device__ int   g_cnt[L];                     // cnt[t] = #words with len > t

// fast transcendentals (err ~1e-7 rel; tolerance is 1e-3)
__device__ __forceinline__ float fsig(float x) {
    return __fdividef(1.f, 1.f + __expf(-x));
}
__device__ __forceinline__ float ftanh(float x) {
    return 1.f - __fdividef(2.f, __expf(2.f * x) + 1.f);
}

__device__ __forceinline__ ull pack2(float x, float y) {
    ull r; asm("mov.b64 %0,{%1,%2};" : "=l"(r) : "f"(x), "f"(y)); return r;
}
__device__ __forceinline__ void unpack2(ull v, float& x, float& y) {
    asm("mov.b64 {%0,%1},%2;" : "=f"(x), "=f"(y) : "l"(v));
}
__device__ __forceinline__ ull ffma2(ull a, ull b, ull c) {
    ull d; asm("fma.rn.f32x2 %0,%1,%2,%3;" : "=l"(d) : "l"(a), "l"(b), "l"(c)); return d;
}

// ---------------- counting sort by char length (descending) ----------------
__global__ void k_sort(const int* __restrict__ lens) {
    __shared__ int hist[17], off[17];
    int tid = threadIdx.x;
    if (tid < 17) hist[tid] = 0;
    __syncthreads();
    for (int s = tid; s < S; s += blockDim.x) atomicAdd(&hist[lens[s]], 1);
    __syncthreads();
    if (tid == 0) {
        int acc = 0;
        for (int l = 16; l >= 1; --l) { off[l] = acc; acc += hist[l]; }
        for (int t = 0; t < L; ++t) g_cnt[t] = off[t + 1] + hist[t + 1];
    }
    __syncthreads();
    for (int s = tid; s < S; s += blockDim.x) {
        int l = lens[s];
        int pos = atomicAdd(&off[l], 1);
        g_perm[pos] = s;
        g_inv[s] = pos;
        g_lensS[pos] = l;
    }
}

// ---------------- fused prep: permuted weights + bias + h/c init -----------------
__global__ void k_prep_all(const float* __restrict__ Wih_c,
                           const float* __restrict__ Whh_c,
                           const float* __restrict__ bih_c,
                           const float* __restrict__ bhh_c,
                           const int*   __restrict__ feat_seq,
                           const float* __restrict__ prefix_emb) {
    int b = blockIdx.x;
    if (b < 5120) {
        int idx = b * 256 + threadIdx.x;               // < 2048*640
        int n = idx / KCAT, k = idx % KCAT;
        int jh = n >> 2, g = n & 3;
        int row = g * H + jh;
        g_Wcat[idx] = (k < EC) ? Wih_c[(size_t)row * EC + k]
                               : Whh_c[(size_t)row * H + (k - EC)];
    } else if (b < 5128) {
        int n = (b - 5120) * 256 + threadIdx.x;        // < 2048
        int jh = n >> 2, g = n & 3;
        int row = g * H + jh;
        g_biasP[n] = bih_c[row] + bhh_c[row];
    } else {
        int idx = (b - 5128) * 256 + threadIdx.x;      // < S*128 (float4 units)
        int j4 = idx & 127;
        int slot = idx >> 7;
        int s = g_perm[slot];
        reinterpret_cast<float4*>(g_hA)[idx] =
            reinterpret_cast<const float4*>(prefix_emb)[(size_t)feat_seq[s] * 128 + j4];
        reinterpret_cast<float4*>(g_c)[idx] = make_float4(0.f, 0.f, 0.f, 0.f);
    }
}

// ---------------- embedding gather (sorted order, float4) ----------------
__global__ void k_gather_xc(const int* __restrict__ chars,
                            const float* __restrict__ char_emb) {
    int idx = blockIdx.x * blockDim.x + threadIdx.x;   // < L*S*32
    int e4 = idx & 31;
    int slot = (idx >> 5) & (S - 1);
    int t = idx >> 17;
    int s = g_perm[slot];
    reinterpret_cast<float4*>(g_Xc)[idx] =
        reinterpret_cast<const float4*>(char_emb)[(size_t)chars[s * L + t] * 32 + e4];
}

__global__ void k_build_wc(const int* __restrict__ word_seq,
                           const float* __restrict__ word_emb) {
    int idx = blockIdx.x * blockDim.x + threadIdx.x;   // < S*256
    int k4 = idx & 255;
    int s = idx >> 8;
    float4 v;
    if (k4 < 128) {
        v = reinterpret_cast<const float4*>(word_emb)[(size_t)word_seq[s] * 128 + k4];
    } else {
        int slot = g_inv[s];
        int len = g_lensS[slot];
        const float4* hp = reinterpret_cast<const float4*>((len & 1) ? g_hB : g_hA);
        v = hp[(size_t)slot * 128 + (k4 - 128)];
    }
    reinterpret_cast<float4*>(g_wc)[idx] = v;
}

// ---------------- fused char-LSTM step: gates GEMM + cell update ----------------
// 128x128 block tile, 8x8 thread tile (FFMA2), double-buffered smem,
// B fragment loaded as 2x LDS.128 (was 4x LDS.64).
__global__ __launch_bounds__(256)
void k_char_step(const float* __restrict__ Xc_t,
                 const float* __restrict__ hcur,
                 float* __restrict__ hnxt, int t) {
    const int cnt = g_cnt[t];
    const int m0 = blockIdx.y * 128;
    if (m0 >= cnt) return;
    const int n0 = blockIdx.x * 128;

    __shared__ __align__(16) float As[2][8][128];
    __shared__ __align__(16) float Bs[2][8][128];

    const int tid = threadIdx.x;
    const int row = tid >> 1;             // 0..127
    const int kc  = (tid & 1) * 4;        // 0 or 4
    const int tx  = tid & 15, ty = tid >> 4;

    ull acc2[8][4];
    #pragma unroll
    for (int i = 0; i < 8; i++)
        #pragma unroll
        for (int j = 0; j < 4; j++) acc2[i][j] = 0ULL;

    float4 pA, pB;
    auto loadT = [&](int kt) {
        int k = kt + kc;
        const float* srcA = (k < EC)
            ? (Xc_t + (size_t)(m0 + row) * EC + k)
            : (hcur + (size_t)(m0 + row) * H + (k - EC));
        pA = *reinterpret_cast<const float4*>(srcA);
        pB = *reinterpret_cast<const float4*>(g_Wcat + (size_t)(n0 + row) * KCAT + k);
    };
    auto stsT = [&](int buf) {
        As[buf][kc + 0][row] = pA.x; As[buf][kc + 1][row] = pA.y;
        As[buf][kc + 2][row] = pA.z; As[buf][kc + 3][row] = pA.w;
        Bs[buf][kc + 0][row] = pB.x; Bs[buf][kc + 1][row] = pB.y;
        Bs[buf][kc + 2][row] = pB.z; Bs[buf][kc + 3][row] = pB.w;
    };

    loadT(0);
    stsT(0);
    __syncthreads();

    int cur = 0;
    for (int kt = 0; kt < KCAT; kt += 8) {
        bool more = (kt + 8) < KCAT;
        if (more) loadT(kt + 8);
        #pragma unroll
        for (int kk = 0; kk < 8; kk++) {
            float a[8];
            *reinterpret_cast<float4*>(&a[0]) = *reinterpret_cast<const float4*>(&As[cur][kk][ty * 8]);
            *reinterpret_cast<float4*>(&a[4]) = *reinterpret_cast<const float4*>(&As[cur][kk][ty * 8 + 4]);
            ull b2[4];
            {
                ulonglong2 b01 = *reinterpret_cast<const ulonglong2*>(&Bs[cur][kk][tx * 8]);
                ulonglong2 b23 = *reinterpret_cast<const ulonglong2*>(&Bs[cur][kk][tx * 8 + 4]);
                b2[0] = b01.x; b2[1] = b01.y; b2[2] = b23.x; b2[3] = b23.y;
            }
            #pragma unroll
            for (int i = 0; i < 8; i++) {
                ull ad = pack2(a[i], a[i]);
                #pragma unroll
                for (int j = 0; j < 4; j++)
                    acc2[i][j] = ffma2(ad, b2[j], acc2[i][j]);
            }
        }
        if (more) {
            stsT(cur ^ 1);
            __syncthreads();
            cur ^= 1;
        }
    }

    float bn[8];
    #pragma unroll
    for (int j = 0; j < 8; j++) bn[j] = g_biasP[n0 + tx * 8 + j];
    const int jh0 = (n0 >> 2) + tx * 2;

    #pragma unroll
    for (int i = 0; i < 8; i++) {
        int m = m0 + ty * 8 + i;
        if (t < g_lensS[m]) {
            float v0, v1, v2, v3, v4, v5, v6, v7;
            unpack2(acc2[i][0], v0, v1); unpack2(acc2[i][1], v2, v3);
            unpack2(acc2[i][2], v4, v5); unpack2(acc2[i][3], v6, v7);
            size_t ci = (size_t)m * H + jh0;
            {
                float iv = v0 + bn[0], fv = v1 + bn[1], gv = v2 + bn[2], ov = v3 + bn[3];
                float c = g_c[ci];
                c = fsig(fv) * c + fsig(iv) * ftanh(gv);
                g_c[ci] = c;
                hnxt[ci] = fsig(ov) * ftanh(c);
            }
            {
                float iv = v4 + bn[4], fv = v5 + bn[5], gv = v6 + bn[6], ov = v7 + bn[7];
                float c = g_c[ci + 1];
                c = fsig(fv) * c + fsig(iv) * ftanh(gv);
                g_c[ci + 1] = c;
                hnxt[ci + 1] = fsig(ov) * ftanh(c);
            }
        }
    }
}

// ---------------- merged x-gate GEMM (fwd + bwd via blockIdx.z) ----------------
__global__ __launch_bounds__(256)
void gemm_xg(const float* __restrict__ A1,
             const float* __restrict__ Bf, const float* __restrict__ Bb,
             const float* __restrict__ b1f, const float* __restrict__ b2f,
             const float* __restrict__ b1b, const float* __restrict__ b2b,
             float* __restrict__ Cf, float* __restrict__ Cb) {
    const int K1 = EW + H, N = G4HH;
    const int BM = 128, BN = 128, BK = 8;
    const float* B1 = blockIdx.z ? Bb : Bf;
    const float* b1 = blockIdx.z ? b1b : b1f;
    const float* b2 = blockIdx.z ? b2b : b2f;
    float* C = blockIdx.z ? Cb : Cf;

    __shared__ __align__(16) float As[BK][BM];
    __shared__ __align__(16) float Bs[BK][BN];
    int tid = threadIdx.x;
    int m0 = blockIdx.y * BM;
    int n0 = blockIdx.x * BN;
    int aRow = tid >> 1, aCol = (tid & 1) * 4;
    int tx = tid & 15, ty = tid >> 4;

    ull acc2[8][4];
    #pragma unroll
    for (int i = 0; i < 8; i++)
        #pragma unroll
        for (int j = 0; j < 4; j++) acc2[i][j] = 0ULL;

    for (int kt = 0; kt < K1; kt += BK) {
        int k = kt + aCol;
        {
            float4 v = *reinterpret_cast<const float4*>(A1 + (size_t)(m0 + aRow) * K1 + k);
            As[aCol + 0][aRow] = v.x; As[aCol + 1][aRow] = v.y;
            As[aCol + 2][aRow] = v.z; As[aCol + 3][aRow] = v.w;
        }
        {
            float4 v = *reinterpret_cast<const float4*>(B1 + (size_t)(n0 + aRow) * K1 + k);
            Bs[aCol + 0][aRow] = v.x; Bs[aCol + 1][aRow] = v.y;
            Bs[aCol + 2][aRow] = v.z; Bs[aCol + 3][aRow] = v.w;
        }
        __syncthreads();
        #pragma unroll
        for (int kk = 0; kk < BK; kk++) {
            float a[8];
            *reinterpret_cast<float4*>(&a[0]) = *reinterpret_cast<const float4*>(&As[kk][ty * 8]);
            *reinterpret_cast<float4*>(&a[4]) = *reinterpret_cast<const float4*>(&As[kk][ty * 8 + 4]);
            ull b2r[4];
            {
                ulonglong2 b01 = *reinterpret_cast<const ulonglong2*>(&Bs[kk][tx * 8]);
                ulonglong2 b23 = *reinterpret_cast<const ulonglong2*>(&Bs[kk][tx * 8 + 4]);
                b2r[0] = b01.x; b2r[1] = b01.y; b2r[2] = b23.x; b2r[3] = b23.y;
            }
            #pragma unroll
            for (int i = 0; i < 8; i++) {
                ull ad = pack2(a[i], a[i]);
                #pragma unroll
                for (int j = 0; j < 4; j++)
                    acc2[i][j] = ffma2(ad, b2r[j], acc2[i][j]);
            }
        }
        __syncthreads();
    }
    #pragma unroll
    for (int i = 0; i < 8; i++) {
        int m = m0 + ty * 8 + i;
        #pragma unroll
        for (int jj = 0; jj < 4; jj++) {
            float lo, hi;
            unpack2(acc2[i][jj], lo, hi);
            int n = n0 + tx * 8 + jj * 2;
            C[(size_t)m * N + n]     = lo + b1[n] + b2[n];
            C[(size_t)m * N + n + 1] = hi + b1[n + 1] + b2[n + 1];
        }
    }
}

// ---------------- word bi-LSTM recurrence: 2 clusters of 8 CTAs, 512 thr ----------
// R9 proven version (two-stage step, warp-0 tail, cluster barrier).
__global__ void __cluster_dims__(8, 1, 1) __launch_bounds__(512, 1)
k_word_lstm(const float* __restrict__ Whh_f, const float* __restrict__ Whh_b) {
    __shared__ __align__(16) float hb[2][HH];
    __shared__ float partial[512];

    unsigned rank;
    asm("mov.u32 %0, %%cluster_ctarank;" : "=r"(rank));
    int dir = blockIdx.x / 8;                   // 0 = fwd, 1 = bwd
    const float* Whh = dir ? Whh_b : Whh_f;
    const float* xg  = dir ? g_xgb : g_xgf;

    int tid = threadIdx.x;
    int p   = tid & 127;       // gate-row within CTA: gate*32 + jj
    int q   = tid >> 7;        // k-quarter (0..3)
    int gte = p >> 5;
    int jj  = p & 31;
    int grow = gte * HH + (int)rank * 32 + jj;  // row in Whh[1024][256]

    ull w2[32];
    const float4* wsrc = reinterpret_cast<const float4*>(Whh + (size_t)grow * HH + q * 64);
    #pragma unroll
    for (int i = 0; i < 16; i++) {
        float4 f = wsrc[i];
        w2[2 * i]     = pack2(f.x, f.y);
        w2[2 * i + 1] = pack2(f.z, f.w);
    }

    int lane = tid & 31;
    unsigned raA[8], raB[8];
    {
        unsigned loff0 = (unsigned)__cvta_generic_to_shared(&hb[0][rank * 32 + lane]);
        unsigned loff1 = (unsigned)__cvta_generic_to_shared(&hb[1][rank * 32 + lane]);
        #pragma unroll
        for (int peer = 0; peer < 8; ++peer) {
            asm("mapa.shared::cluster.u32 %0, %1, %2;" : "=r"(raA[peer]) : "r"(loff0), "r"(peer));
            asm("mapa.shared::cluster.u32 %0, %1, %2;" : "=r"(raB[peer]) : "r"(loff1), "r"(peer));
        }
    }

    if (tid < HH) hb[0][tid] = 0.f;
    __syncthreads();
    asm volatile("barrier.cluster.arrive.aligned;" ::: "memory");
    asm volatile("barrier.cluster.wait.aligned;"   ::: "memory");

    float c_reg = 0.f;
    int par = 0;
    const int xbase = (int)rank * 32 + lane;   // x-gate column base (warp-0 lanes)
    float xv0 = 0.f, xv1 = 0.f, xv2 = 0.f, xv3 = 0.f;
    if (tid < 32) {
        size_t r0 = (size_t)(dir ? (S - 1) : 0) * G4HH + xbase;
        xv0 = __ldg(&xg[r0]);       xv1 = __ldg(&xg[r0 + 256]);
        xv2 = __ldg(&xg[r0 + 512]); xv3 = __ldg(&xg[r0 + 768]);
    }

    for (int t = 0; t < S; ++t) {
        int row = dir ? (S - 1 - t) : t;

        const ull* hv = reinterpret_cast<const ull*>(&hb[par][q * 64]);
        ull a0 = 0ULL, a1 = 0ULL, a2 = 0ULL, a3 = 0ULL;
        #pragma unroll
        for (int i = 0; i < 32; i += 4) {
            a0 = ffma2(w2[i + 0], hv[i + 0], a0);
            a1 = ffma2(w2[i + 1], hv[i + 1], a1);
            a2 = ffma2(w2[i + 2], hv[i + 2], a2);
            a3 = ffma2(w2[i + 3], hv[i + 3], a3);
        }
        float l0, h0f, l1, h1f, l2, h2f, l3, h3f;
        unpack2(a0, l0, h0f); unpack2(a1, l1, h1f);
        unpack2(a2, l2, h2f); unpack2(a3, l3, h3f);
        partial[tid] = ((l0 + h0f) + (l1 + h1f)) + ((l2 + h2f) + (l3 + h3f));

        float nx0 = 0.f, nx1 = 0.f, nx2 = 0.f, nx3 = 0.f;
        if (tid < 32 && t + 1 < S) {
            int rn = dir ? (S - 2 - t) : (t + 1);
            size_t rb = (size_t)rn * G4HH + xbase;
            nx0 = __ldg(&xg[rb]);       nx1 = __ldg(&xg[rb + 256]);
            nx2 = __ldg(&xg[rb + 512]); nx3 = __ldg(&xg[rb + 768]);
        }
        __syncthreads();
        if (tid < 32) {
            float p0 = (partial[lane]       + partial[lane + 128])
                     + (partial[lane + 256] + partial[lane + 384]);
            float p1 = (partial[32 + lane]       + partial[32 + lane + 128])
                     + (partial[32 + lane + 256] + partial[32 + lane + 384]);
            float p2 = (partial[64 + lane]       + partial[64 + lane + 128])
                     + (partial[64 + lane + 256] + partial[64 + lane + 384]);
            float p3 = (partial[96 + lane]       + partial[96 + lane + 128])
                     + (partial[96 + lane + 256] + partial[96 + lane + 384]);
            float iv = fsig(p0 + xv0);
            float fv = fsig(p1 + xv1);
            float gg = ftanh(p2 + xv2);
            float ov = fsig(p3 + xv3);
            c_reg = fv * c_reg + iv * gg;
            float hnew = ov * ftanh(c_reg);
            g_out[(size_t)row * H + dir * HH + rank * 32 + lane] = hnew;
            if (par == 0) {
                #pragma unroll
                for (int peer = 0; peer < 8; ++peer)
                    asm volatile("st.shared::cluster.f32 [%0], %1;"
                                 :: "r"(raB[peer]), "f"(hnew) : "memory");
            } else {
                #pragma unroll
                for (int peer = 0; peer < 8; ++peer)
                    asm volatile("st.shared::cluster.f32 [%0], %1;"
                                 :: "r"(raA[peer]), "f"(hnew) : "memory");
            }
        }
        asm volatile("barrier.cluster.arrive.aligned;" ::: "memory");
        asm volatile("barrier.cluster.wait.aligned;"   ::: "memory");
        par ^= 1;
        xv0 = nx0; xv1 = nx1; xv2 = nx2; xv3 = nx3;
    }
}

// ---------------- output heads: logits + log_softmax ----------------
__global__ void k_logits(const float* __restrict__ W,   // [C,512]
                         const float* __restrict__ bias,
                         float* __restrict__ dst, int C) {
    __shared__ float row[H];
    __shared__ float red[64];
    int s = blockIdx.x, tid = threadIdx.x;
    for (int k = tid; k < H; k += blockDim.x) row[k] = g_out[(size_t)s * H + k];
    __syncthreads();
    float acc = bias[tid];
    const float4* w4 = reinterpret_cast<const float4*>(W + (size_t)tid * H);
    const float4* r4 = reinterpret_cast<const float4*>(row);
    #pragma unroll 8
    for (int q = 0; q < H / 4; q++) {
        float4 w = w4[q], r = r4[q];
        acc += w.x * r.x + w.y * r.y + w.z * r.z + w.w * r.w;
    }
    red[tid] = acc;
    __syncthreads();
    for (int off = C >> 1; off; off >>= 1) {
        if (tid < off) red[tid] = fmaxf(red[tid], red[tid + off]);
        __syncthreads();
    }
    float mx = red[0];
    __syncthreads();
    red[tid] = expf(acc - mx);
    __syncthreads();
    for (int off = C >> 1; off; off >>= 1) {
        if (tid < off) red[tid] += red[tid + off];
        __syncthreads();
    }
    float lse = mx + logf(red[0]);
    dst[(size_t)s * C + tid] = acc - lse;
}

// ---------------- launch ----------------
extern "C" void kernel_launch(void* const* d_in, const int* in_sizes, int n_in,
                              void* d_out, int out_size) {
    const int*   word_seq   = (const int*)  d_in[0];
    const int*   chars      = (const int*)  d_in[1];
    const int*   char_lens  = (const int*)  d_in[2];
    const int*   feat_seq   = (const int*)  d_in[3];
    const float* char_emb   = (const float*)d_in[4];
    const float* word_emb   = (const float*)d_in[5];
    const float* prefix_emb = (const float*)d_in[6];
    const float* Wih_c = (const float*)d_in[7];
    const float* Whh_c = (const float*)d_in[8];
    const float* bih_c = (const float*)d_in[9];
    const float* bhh_c = (const float*)d_in[10];
    const float* Wih_f = (const float*)d_in[11];
    const float* Whh_f = (const float*)d_in[12];
    const float* bih_f = (const float*)d_in[13];
    const float* bhh_f = (const float*)d_in[14];
    const float* Wih_b = (const float*)d_in[15];
    const float* Whh_b = (const float*)d_in[16];
    const float* bih_b = (const float*)d_in[17];
    const float* bhh_b = (const float*)d_in[18];
    const float* Wpos  = (const float*)d_in[19];
    const float* bpos  = (const float*)d_in[20];
    const float* Wner  = (const float*)d_in[21];
    const float* bner  = (const float*)d_in[22];
    float* out = (float*)d_out;

    float *p_Xc, *p_hA, *p_hB, *p_wc, *p_xgf, *p_xgb;
    cudaGetSymbolAddress((void**)&p_Xc,  g_Xc);
    cudaGetSymbolAddress((void**)&p_hA,  g_hA);
    cudaGetSymbolAddress((void**)&p_hB,  g_hB);
    cudaGetSymbolAddress((void**)&p_wc,  g_wc);
    cudaGetSymbolAddress((void**)&p_xgf, g_xgf);
    cudaGetSymbolAddress((void**)&p_xgb, g_xgb);

    // launches 1-3: sort, fused prep, gather
    k_sort<<<1, 256>>>(char_lens);
    k_prep_all<<<5120 + 8 + 2048, 256>>>(Wih_c, Whh_c, bih_c, bhh_c,
                                         feat_seq, prefix_emb);
    k_gather_xc<<<(L * S * 32) / 256, 256>>>(chars, char_emb);

    // char LSTM: 16 fused steps (128x128 tile), h ping-pong, early-exit
    dim3 gridC(G4H / 128, S / 128);
    for (int t = 0; t < L; ++t) {
        float* hcur = (t & 1) ? p_hB : p_hA;
        float* hnxt = (t & 1) ? p_hA : p_hB;
        k_char_step<<<gridC, 256>>>(p_Xc + (size_t)t * S * EC, hcur, hnxt, t);
    }

    // word LSTM input + merged x-gate precompute (fwd+bwd in one launch)
    k_build_wc<<<(S * 256) / 256, 256>>>(word_seq, word_emb);
    dim3 gridX(G4HH / 128, S / 128, 2);
    gemm_xg<<<gridX, 256>>>(p_wc, Wih_f, Wih_b,
                            bih_f, bhh_f, bih_b, bhh_b,
                            p_xgf, p_xgb);

    // sequential bi-LSTM recurrence (2 clusters of 8 CTAs, fwd + bwd concurrent)
    k_word_lstm<<<16, 512>>>(Whh_f, Whh_b);

    // output heads
    k_logits<<<S, NPOS>>>(Wpos, bpos, out, NPOS);
    k_logits<<<S, NNER>>>(Wner, bner, out + (size_t)S * NPOS, NNER);

    (void)in_sizes; (void)n_in; (void)out_size;
}

// round 13
// speedup vs baseline: 1.2521x; 1.1886x over previous
#include <cuda_runtime.h>
#include <cuda_bf16.h>
#include <cstdint>
#include <cstddef>
#include <math.h>

#define S    4096
#define L    16
#define H    512
#define EC   128
#define EW   512
#define HH   256
#define G4H  2048   // 4*H
#define G4HH 1024   // 4*HH
#define NPOS 64
#define NNER 32
#define KCAT 640    // EC + H

typedef unsigned long long ull;

// ---------------- scratch (device globals; no dynamic allocation) ----------------
__device__ __nv_bfloat16 g_xc16h[(size_t)L * S * EC];  // char embeddings bf16-hi
__device__ __nv_bfloat16 g_xc16l[(size_t)L * S * EC];  // bf16-lo
__device__ __nv_bfloat16 g_h16hA[(size_t)S * H];       // h bf16-hi ping
__device__ __nv_bfloat16 g_h16lA[(size_t)S * H];       // h bf16-lo ping
__device__ __nv_bfloat16 g_h16hB[(size_t)S * H];       // h bf16-hi pong
__device__ __nv_bfloat16 g_h16lB[(size_t)S * H];       // h bf16-lo pong
__device__ __nv_bfloat16 g_w16h[(size_t)G4H * KCAT];   // permuted Wcat bf16-hi
__device__ __nv_bfloat16 g_w16l[(size_t)G4H * KCAT];   // permuted Wcat bf16-lo
__device__ float g_hA[(size_t)S * H];          // char LSTM hidden fp32 ping
__device__ float g_hB[(size_t)S * H];          // char LSTM hidden fp32 pong
__device__ float g_c [(size_t)S * H];          // char LSTM cell (sorted order)
__device__ float g_wc [(size_t)S * (EW + H)];  // word LSTM input [S,1024] (orig order)
__device__ float g_xgf[(size_t)S * G4HH];      // precomputed x-gates fwd
__device__ float g_xgb[(size_t)S * G4HH];      // precomputed x-gates bwd
__device__ float g_out[(size_t)S * H];         // bi-LSTM output [S,512]
__device__ float g_biasP[G4H];                 // permuted bih_c+bhh_c
__device__ int   g_perm[S];                    // sorted slot -> original index
__device__ int   g_inv[S];                     // original index -> sorted slot
__device__ int   g_lensS[S];                   // lens in sorted order (descending)
__device__ int   g_cnt[L];                     // cnt[t] = #words with len > t

// fast transcendentals (err ~1e-7 rel; tolerance is 1e-3)
__device__ __forceinline__ float fsig(float x) {
    return __fdividef(1.f, 1.f + __expf(-x));
}
__device__ __forceinline__ float ftanh(float x) {
    return 1.f - __fdividef(2.f, __expf(2.f * x) + 1.f);
}

__device__ __forceinline__ ull pack2(float x, float y) {
    ull r; asm("mov.b64 %0,{%1,%2};" : "=l"(r) : "f"(x), "f"(y)); return r;
}
__device__ __forceinline__ void unpack2(ull v, float& x, float& y) {
    asm("mov.b64 {%0,%1},%2;" : "=f"(x), "=f"(y) : "l"(v));
}
__device__ __forceinline__ ull ffma2(ull a, ull b, ull c) {
    ull d; asm("fma.rn.f32x2 %0,%1,%2,%3;" : "=l"(d) : "l"(a), "l"(b), "l"(c)); return d;
}

#define SMEM_SWIZZLE_128B(bo) ((bo) ^ (((bo) >> 3) & 0x70))

// ---------------- counting sort by char length (descending) ----------------
__global__ void k_sort(const int* __restrict__ lens) {
    __shared__ int hist[17], off[17];
    int tid = threadIdx.x;
    if (tid < 17) hist[tid] = 0;
    __syncthreads();
    for (int s = tid; s < S; s += blockDim.x) atomicAdd(&hist[lens[s]], 1);
    __syncthreads();
    if (tid == 0) {
        int acc = 0;
        for (int l = 16; l >= 1; --l) { off[l] = acc; acc += hist[l]; }
        for (int t = 0; t < L; ++t) g_cnt[t] = off[t + 1] + hist[t + 1];
    }
    __syncthreads();
    for (int s = tid; s < S; s += blockDim.x) {
        int l = lens[s];
        int pos = atomicAdd(&off[l], 1);
        g_perm[pos] = s;
        g_inv[s] = pos;
        g_lensS[pos] = l;
    }
}

// ---------------- fused prep: bf16 weights + bias + h/c init -----------------
__global__ void k_prep_all(const float* __restrict__ Wih_c,
                           const float* __restrict__ Whh_c,
                           const float* __restrict__ bih_c,
                           const float* __restrict__ bhh_c,
                           const int*   __restrict__ feat_seq,
                           const float* __restrict__ prefix_emb) {
    int b = blockIdx.x;
    if (b < 5120) {
        int idx = b * 256 + threadIdx.x;               // < 2048*640
        int n = idx / KCAT, k = idx % KCAT;
        int jh = n >> 2, g = n & 3;
        int row = g * H + jh;
        float w = (k < EC) ? Wih_c[(size_t)row * EC + k]
                           : Whh_c[(size_t)row * H + (k - EC)];
        __nv_bfloat16 hi = __float2bfloat16(w);
        g_w16h[idx] = hi;
        g_w16l[idx] = __float2bfloat16(w - __bfloat162float(hi));
    } else if (b < 5128) {
        int n = (b - 5120) * 256 + threadIdx.x;        // < 2048
        int jh = n >> 2, g = n & 3;
        int row = g * H + jh;
        g_biasP[n] = bih_c[row] + bhh_c[row];
    } else {
        int idx = (b - 5128) * 256 + threadIdx.x;      // < S*512
        int j = idx & 511;
        int slot = idx >> 9;
        int s = g_perm[slot];
        float h0 = prefix_emb[(size_t)s * H + j];
        g_hA[idx] = h0;
        __nv_bfloat16 hi = __float2bfloat16(h0);
        g_h16hA[idx] = hi;
        g_h16lA[idx] = __float2bfloat16(h0 - __bfloat162float(hi));
        g_c[idx] = 0.f;
    }
}

// NOTE: k_prep_all h0 init uses prefix_emb[feat_seq[s]]
// (bug guard: see launch — feat_seq indexing handled there via lookup kernel)
__global__ void k_fix_h0(const int* __restrict__ feat_seq,
                         const float* __restrict__ prefix_emb) {
    int idx = blockIdx.x * blockDim.x + threadIdx.x;   // < S*512
    int j = idx & 511;
    int slot = idx >> 9;
    int s = g_perm[slot];
    float h0 = prefix_emb[(size_t)feat_seq[s] * H + j];
    g_hA[idx] = h0;
    __nv_bfloat16 hi = __float2bfloat16(h0);
    g_h16hA[idx] = hi;
    g_h16lA[idx] = __float2bfloat16(h0 - __bfloat162float(hi));
    g_c[idx] = 0.f;
}

// ---------------- embedding gather: char emb -> bf16 hi/lo (sorted order) -------
__global__ void k_gather_xc(const int* __restrict__ chars,
                            const float* __restrict__ char_emb) {
    int idx = blockIdx.x * blockDim.x + threadIdx.x;   // < L*S*64 (pairs)
    int e2 = idx & 63;
    int slot = (idx >> 6) & (S - 1);
    int t = idx >> 18;
    int s = g_perm[slot];
    float2 v = *reinterpret_cast<const float2*>(
        char_emb + (size_t)chars[s * L + t] * EC + e2 * 2);
    __nv_bfloat16 h0 = __float2bfloat16(v.x), h1 = __float2bfloat16(v.y);
    __nv_bfloat16 l0 = __float2bfloat16(v.x - __bfloat162float(h0));
    __nv_bfloat16 l1 = __float2bfloat16(v.y - __bfloat162float(h1));
    reinterpret_cast<__nv_bfloat162*>(g_xc16h)[idx] = __nv_bfloat162(h0, h1);
    reinterpret_cast<__nv_bfloat162*>(g_xc16l)[idx] = __nv_bfloat162(l0, l1);
}

__global__ void k_build_wc(const int* __restrict__ word_seq,
                           const float* __restrict__ word_emb) {
    int idx = blockIdx.x * blockDim.x + threadIdx.x;   // < S*256
    int k4 = idx & 255;
    int s = idx >> 8;
    float4 v;
    if (k4 < 128) {
        v = reinterpret_cast<const float4*>(word_emb)[(size_t)word_seq[s] * 128 + k4];
    } else {
        int slot = g_inv[s];
        int len = g_lensS[slot];
        const float4* hp = reinterpret_cast<const float4*>((len & 1) ? g_hB : g_hA);
        v = hp[(size_t)slot * 128 + (k4 - 128)];
    }
    reinterpret_cast<float4*>(g_wc)[idx] = v;
}

// ---------------- char-LSTM step via mma.sync bf16 (split hi/lo) + cell --------
// 128(M)x128(N) CTA tile; K'' = 1920 bf16 across 3 split passes
// (blk0: Ah*Bh, blk1: Ah*Bl, blk2: Al*Bh). 30 stages of K=64 staged in
// SW128-swizzled smem (128B rows); ldmatrix + mma.m16n8k16.row.col.
// 8 warps = 2(m) x 4(n); warp tile m64 x n32. Epilogue via padded smem.
#define SM_BIAS 0
#define SM_A    1024
#define SM_B    (1024 + 16384)
#define SM_G    1024
#define GPITCH  132
#define SMEM_MMA_BYTES (1024 + 128 * GPITCH * 4 + 1024)

__global__ __launch_bounds__(256)
void k_char_mma(const __nv_bfloat16* __restrict__ xh,
                const __nv_bfloat16* __restrict__ xl,
                const __nv_bfloat16* __restrict__ hch,
                const __nv_bfloat16* __restrict__ hcl,
                __nv_bfloat16* __restrict__ hnh,
                __nv_bfloat16* __restrict__ hnl,
                float* __restrict__ hnf,
                int t) {
    extern __shared__ char smem_raw[];
    const int cnt = g_cnt[t];
    const int m0 = blockIdx.y * 128;
    if (m0 >= cnt) return;
    const int n0 = blockIdx.x * 128;

    char* smem = reinterpret_cast<char*>(
        (((uintptr_t)smem_raw) + 1023) & ~(uintptr_t)1023);
    uint32_t sb = (uint32_t)__cvta_generic_to_shared(smem);

    const int tid = threadIdx.x;
    const int wid = tid >> 5, lane = tid & 31;
    float* sbias = reinterpret_cast<float*>(smem + SM_BIAS);
    if (tid < 128) sbias[tid] = g_biasP[n0 + tid];

    const int wm = wid >> 2;       // 0..1  (m block of 64)
    const int wn = wid & 3;        // 0..3  (n block of 32)

    float acc[4][4][4];
    #pragma unroll
    for (int i = 0; i < 4; i++)
        #pragma unroll
        for (int j = 0; j < 4; j++)
            #pragma unroll
            for (int k = 0; k < 4; k++) acc[i][j][k] = 0.f;

    // staging indices: each thread stores 4x 16B per operand
    const int lr = tid >> 3;            // 0..31 row group
    const int lc = tid & 7;             // 16B chunk within 128B row

    // precomputed ldmatrix smem addresses (swizzled), per k16-step computed inline
    const int a_row = wm * 64 + ((lane >> 3) & 1) * 8 + (lane & 7);   // + mt*16
    const int a_kb  = (lane >> 4) * 16;                               // + ks*32
    const int b_row = wn * 32 + (lane & 7);                           // + nt*8
    const int b_kb  = ((lane >> 3) & 1) * 16;                         // + ks*32

    for (int s = 0; s < 30; ++s) {
        int kk0 = s * 64;
        int blk = kk0 / 640;
        int ko  = kk0 - blk * 640;
        const __nv_bfloat16* Ab;
        int astr;
        if (ko < EC) { Ab = (blk < 2 ? xh : xl) + ko; astr = EC; }
        else         { Ab = (blk < 2 ? hch : hcl) + (ko - EC); astr = H; }
        const __nv_bfloat16* Bb = (blk == 1 ? g_w16l : g_w16h) + ko;

        __syncthreads();   // previous stage's fragments fully consumed
        #pragma unroll
        for (int p = 0; p < 4; ++p) {
            int r = p * 32 + lr;
            uint4 va = *reinterpret_cast<const uint4*>(Ab + (size_t)(m0 + r) * astr + lc * 8);
            uint4 vb = *reinterpret_cast<const uint4*>(Bb + (size_t)(n0 + r) * KCAT + lc * 8);
            uint32_t so = SMEM_SWIZZLE_128B((uint32_t)(r * 128 + lc * 16));
            *reinterpret_cast<uint4*>(smem + SM_A + so) = va;
            *reinterpret_cast<uint4*>(smem + SM_B + so) = vb;
        }
        __syncthreads();

        #pragma unroll
        for (int ks = 0; ks < 4; ++ks) {
            uint32_t afr[4][4];
            #pragma unroll
            for (int mt = 0; mt < 4; ++mt) {
                uint32_t ad = sb + SM_A + SMEM_SWIZZLE_128B(
                    (uint32_t)((a_row + mt * 16) * 128 + ks * 32 + a_kb));
                asm volatile("ldmatrix.sync.aligned.m8n8.x4.shared.b16 {%0,%1,%2,%3}, [%4];"
                             : "=r"(afr[mt][0]), "=r"(afr[mt][1]),
                               "=r"(afr[mt][2]), "=r"(afr[mt][3]) : "r"(ad));
            }
            uint32_t bfr[4][2];
            #pragma unroll
            for (int nt = 0; nt < 4; ++nt) {
                uint32_t bd = sb + SM_B + SMEM_SWIZZLE_128B(
                    (uint32_t)((b_row + nt * 8) * 128 + ks * 32 + b_kb));
                asm volatile("ldmatrix.sync.aligned.m8n8.x2.shared.b16 {%0,%1}, [%2];"
                             : "=r"(bfr[nt][0]), "=r"(bfr[nt][1]) : "r"(bd));
            }
            #pragma unroll
            for (int mt = 0; mt < 4; ++mt)
                #pragma unroll
                for (int nt = 0; nt < 4; ++nt) {
                    asm volatile(
                        "mma.sync.aligned.m16n8k16.row.col.f32.bf16.bf16.f32 "
                        "{%0,%1,%2,%3}, {%4,%5,%6,%7}, {%8,%9}, {%0,%1,%2,%3};"
                        : "+f"(acc[mt][nt][0]), "+f"(acc[mt][nt][1]),
                          "+f"(acc[mt][nt][2]), "+f"(acc[mt][nt][3])
                        : "r"(afr[mt][0]), "r"(afr[mt][1]),
                          "r"(afr[mt][2]), "r"(afr[mt][3]),
                          "r"(bfr[nt][0]), "r"(bfr[nt][1]));
                }
        }
    }
    __syncthreads();

    // accumulators -> padded smem gates buffer
    float* gsm = reinterpret_cast<float*>(smem + SM_G);
    {
        int gr = lane >> 2;            // 0..7
        int gc0 = 2 * (lane & 3);
        #pragma unroll
        for (int mt = 0; mt < 4; ++mt)
            #pragma unroll
            for (int nt = 0; nt < 4; ++nt) {
                int r0 = wm * 64 + mt * 16 + gr;
                int c  = wn * 32 + nt * 8 + gc0;
                gsm[r0 * GPITCH + c]       = acc[mt][nt][0];
                gsm[r0 * GPITCH + c + 1]   = acc[mt][nt][1];
                gsm[(r0 + 8) * GPITCH + c]     = acc[mt][nt][2];
                gsm[(r0 + 8) * GPITCH + c + 1] = acc[mt][nt][3];
            }
    }
    __syncthreads();

    // fused LSTM cell update: 2 threads per row, 16 units each
    {
        int r = tid >> 1, half = tid & 1;
        int m = m0 + r;
        if (t < g_lensS[m]) {
            const float* grow = gsm + r * GPITCH + half * 64;
            const float* brow = sbias + half * 64;
            size_t ci = (size_t)m * H + (n0 >> 2) + half * 16;
            #pragma unroll
            for (int u = 0; u < 16; ++u) {
                float iv = grow[4 * u + 0] + brow[4 * u + 0];
                float fv = grow[4 * u + 1] + brow[4 * u + 1];
                float gv = grow[4 * u + 2] + brow[4 * u + 2];
                float ov = grow[4 * u + 3] + brow[4 * u + 3];
                float cc = g_c[ci + u];
                cc = fsig(fv) * cc + fsig(iv) * ftanh(gv);
                g_c[ci + u] = cc;
                float hh = fsig(ov) * ftanh(cc);
                hnf[ci + u] = hh;
                __nv_bfloat16 hb16 = __float2bfloat16(hh);
                hnh[ci + u] = hb16;
                hnl[ci + u] = __float2bfloat16(hh - __bfloat162float(hb16));
            }
        }
    }
}

// ---------------- merged x-gate GEMM (fwd + bwd via blockIdx.z) ----------------
__global__ __launch_bounds__(256)
void gemm_xg(const float* __restrict__ A1,
             const float* __restrict__ Bf, const float* __restrict__ Bb,
             const float* __restrict__ b1f, const float* __restrict__ b2f,
             const float* __restrict__ b1b, const float* __restrict__ b2b,
             float* __restrict__ Cf, float* __restrict__ Cb) {
    const int K1 = EW + H, N = G4HH;
    const int BM = 128, BN = 128, BK = 8;
    const float* B1 = blockIdx.z ? Bb : Bf;
    const float* b1 = blockIdx.z ? b1b : b1f;
    const float* b2 = blockIdx.z ? b2b : b2f;
    float* C = blockIdx.z ? Cb : Cf;

    __shared__ __align__(16) float As[BK][BM];
    __shared__ __align__(16) float Bs[BK][BN];
    int tid = threadIdx.x;
    int m0 = blockIdx.y * BM;
    int n0 = blockIdx.x * BN;
    int aRow = tid >> 1, aCol = (tid & 1) * 4;
    int tx = tid & 15, ty = tid >> 4;

    ull acc2[8][4];
    #pragma unroll
    for (int i = 0; i < 8; i++)
        #pragma unroll
        for (int j = 0; j < 4; j++) acc2[i][j] = 0ULL;

    for (int kt = 0; kt < K1; kt += BK) {
        int k = kt + aCol;
        {
            float4 v = *reinterpret_cast<const float4*>(A1 + (size_t)(m0 + aRow) * K1 + k);
            As[aCol + 0][aRow] = v.x; As[aCol + 1][aRow] = v.y;
            As[aCol + 2][aRow] = v.z; As[aCol + 3][aRow] = v.w;
        }
        {
            float4 v = *reinterpret_cast<const float4*>(B1 + (size_t)(n0 + aRow) * K1 + k);
            Bs[aCol + 0][aRow] = v.x; Bs[aCol + 1][aRow] = v.y;
            Bs[aCol + 2][aRow] = v.z; Bs[aCol + 3][aRow] = v.w;
        }
        __syncthreads();
        #pragma unroll
        for (int kk = 0; kk < BK; kk++) {
            float a[8];
            *reinterpret_cast<float4*>(&a[0]) = *reinterpret_cast<const float4*>(&As[kk][ty * 8]);
            *reinterpret_cast<float4*>(&a[4]) = *reinterpret_cast<const float4*>(&As[kk][ty * 8 + 4]);
            ull b2r[4];
            const ull* bp = reinterpret_cast<const ull*>(&Bs[kk][tx * 8]);
            b2r[0] = bp[0]; b2r[1] = bp[1]; b2r[2] = bp[2]; b2r[3] = bp[3];
            #pragma unroll
            for (int i = 0; i < 8; i++) {
                ull ad = pack2(a[i], a[i]);
                #pragma unroll
                for (int j = 0; j < 4; j++)
                    acc2[i][j] = ffma2(ad, b2r[j], acc2[i][j]);
            }
        }
        __syncthreads();
    }
    #pragma unroll
    for (int i = 0; i < 8; i++) {
        int m = m0 + ty * 8 + i;
        #pragma unroll
        for (int jj = 0; jj < 4; jj++) {
            float lo, hi;
            unpack2(acc2[i][jj], lo, hi);
            int n = n0 + tx * 8 + jj * 2;
            C[(size_t)m * N + n]     = lo + b1[n] + b2[n];
            C[(size_t)m * N + n + 1] = hi + b1[n + 1] + b2[n + 1];
        }
    }
}

// ---------------- word bi-LSTM recurrence: 2 clusters of 8 CTAs, 512 thr ----------
__global__ void __cluster_dims__(8, 1, 1) __launch_bounds__(512, 1)
k_word_lstm(const float* __restrict__ Whh_f, const float* __restrict__ Whh_b) {
    __shared__ __align__(16) float hb[2][HH];
    __shared__ float partial[512];

    unsigned rank;
    asm("mov.u32 %0, %%cluster_ctarank;" : "=r"(rank));
    int dir = blockIdx.x / 8;
    const float* Whh = dir ? Whh_b : Whh_f;
    const float* xg  = dir ? g_xgb : g_xgf;

    int tid = threadIdx.x;
    int p   = tid & 127;
    int q   = tid >> 7;
    int gte = p >> 5;
    int jj  = p & 31;
    int grow = gte * HH + (int)rank * 32 + jj;

    ull w2[32];
    const float4* wsrc = reinterpret_cast<const float4*>(Whh + (size_t)grow * HH + q * 64);
    #pragma unroll
    for (int i = 0; i < 16; i++) {
        float4 f = wsrc[i];
        w2[2 * i]     = pack2(f.x, f.y);
        w2[2 * i + 1] = pack2(f.z, f.w);
    }

    int lane = tid & 31;
    unsigned raA[8], raB[8];
    {
        unsigned loff0 = (unsigned)__cvta_generic_to_shared(&hb[0][rank * 32 + lane]);
        unsigned loff1 = (unsigned)__cvta_generic_to_shared(&hb[1][rank * 32 + lane]);
        #pragma unroll
        for (int peer = 0; peer < 8; ++peer) {
            asm("mapa.shared::cluster.u32 %0, %1, %2;" : "=r"(raA[peer]) : "r"(loff0), "r"(peer));
            asm("mapa.shared::cluster.u32 %0, %1, %2;" : "=r"(raB[peer]) : "r"(loff1), "r"(peer));
        }
    }

    if (tid < HH) hb[0][tid] = 0.f;
    __syncthreads();
    asm volatile("barrier.cluster.arrive.aligned;" ::: "memory");
    asm volatile("barrier.cluster.wait.aligned;"   ::: "memory");

    float c_reg = 0.f;
    int par = 0;
    const int xbase = (int)rank * 32 + lane;
    float xv0 = 0.f, xv1 = 0.f, xv2 = 0.f, xv3 = 0.f;
    if (tid < 32) {
        size_t r0 = (size_t)(dir ? (S - 1) : 0) * G4HH + xbase;
        xv0 = __ldg(&xg[r0]);       xv1 = __ldg(&xg[r0 + 256]);
        xv2 = __ldg(&xg[r0 + 512]); xv3 = __ldg(&xg[r0 + 768]);
    }

    for (int t = 0; t < S; ++t) {
        int row = dir ? (S - 1 - t) : t;

        const ull* hv = reinterpret_cast<const ull*>(&hb[par][q * 64]);
        ull a0 = 0ULL, a1 = 0ULL, a2 = 0ULL, a3 = 0ULL;
        #pragma unroll
        for (int i = 0; i < 32; i += 4) {
            a0 = ffma2(w2[i + 0], hv[i + 0], a0);
            a1 = ffma2(w2[i + 1], hv[i + 1], a1);
            a2 = ffma2(w2[i + 2], hv[i + 2], a2);
            a3 = ffma2(w2[i + 3], hv[i + 3], a3);
        }
        float l0, h0f, l1, h1f, l2, h2f, l3, h3f;
        unpack2(a0, l0, h0f); unpack2(a1, l1, h1f);
        unpack2(a2, l2, h2f); unpack2(a3, l3, h3f);
        partial[tid] = ((l0 + h0f) + (l1 + h1f)) + ((l2 + h2f) + (l3 + h3f));

        float nx0 = 0.f, nx1 = 0.f, nx2 = 0.f, nx3 = 0.f;
        if (tid < 32 && t + 1 < S) {
            int rn = dir ? (S - 2 - t) : (t + 1);
            size_t rb = (size_t)rn * G4HH + xbase;
            nx0 = __ldg(&xg[rb]);       nx1 = __ldg(&xg[rb + 256]);
            nx2 = __ldg(&xg[rb + 512]); nx3 = __ldg(&xg[rb + 768]);
        }
        __syncthreads();
        if (tid < 32) {
            float p0 = (partial[lane]       + partial[lane + 128])
                     + (partial[lane + 256] + partial[lane + 384]);
            float p1 = (partial[32 + lane]       + partial[32 + lane + 128])
                     + (partial[32 + lane + 256] + partial[32 + lane + 384]);
            float p2 = (partial[64 + lane]       + partial[64 + lane + 128])
                     + (partial[64 + lane + 256] + partial[64 + lane + 384]);
            float p3 = (partial[96 + lane]       + partial[96 + lane + 128])
                     + (partial[96 + lane + 256] + partial[96 + lane + 384]);
            float iv = fsig(p0 + xv0);
            float fv = fsig(p1 + xv1);
            float gg = ftanh(p2 + xv2);
            float ov = fsig(p3 + xv3);
            c_reg = fv * c_reg + iv * gg;
            float hnew = ov * ftanh(c_reg);
            g_out[(size_t)row * H + dir * HH + rank * 32 + lane] = hnew;
            if (par == 0) {
                #pragma unroll
                for (int peer = 0; peer < 8; ++peer)
                    asm volatile("st.shared::cluster.f32 [%0], %1;"
                                 :: "r"(raB[peer]), "f"(hnew) : "memory");
            } else {
                #pragma unroll
                for (int peer = 0; peer < 8; ++peer)
                    asm volatile("st.shared::cluster.f32 [%0], %1;"
                                 :: "r"(raA[peer]), "f"(hnew) : "memory");
            }
        }
        asm volatile("barrier.cluster.arrive.aligned;" ::: "memory");
        asm volatile("barrier.cluster.wait.aligned;"   ::: "memory");
        par ^= 1;
        xv0 = nx0; xv1 = nx1; xv2 = nx2; xv3 = nx3;
    }
}

// ---------------- output heads: logits + log_softmax ----------------
__global__ void k_logits(const float* __restrict__ W,   // [C,512]
                         const float* __restrict__ bias,
                         float* __restrict__ dst, int C) {
    __shared__ float row[H];
    __shared__ float red[64];
    int s = blockIdx.x, tid = threadIdx.x;
    for (int k = tid; k < H; k += blockDim.x) row[k] = g_out[(size_t)s * H + k];
    __syncthreads();
    float acc = bias[tid];
    const float4* w4 = reinterpret_cast<const float4*>(W + (size_t)tid * H);
    const float4* r4 = reinterpret_cast<const float4*>(row);
    #pragma unroll 8
    for (int q = 0; q < H / 4; q++) {
        float4 w = w4[q], r = r4[q];
        acc += w.x * r.x + w.y * r.y + w.z * r.z + w.w * r.w;
    }
    red[tid] = acc;
    __syncthreads();
    for (int off = C >> 1; off; off >>= 1) {
        if (tid < off) red[tid] = fmaxf(red[tid], red[tid + off]);
        __syncthreads();
    }
    float mx = red[0];
    __syncthreads();
    red[tid] = expf(acc - mx);
    __syncthreads();
    for (int off = C >> 1; off; off >>= 1) {
        if (tid < off) red[tid] += red[tid + off];
        __syncthreads();
    }
    float lse = mx + logf(red[0]);
    dst[(size_t)s * C + tid] = acc - lse;
}

// ---------------- launch ----------------
extern "C" void kernel_launch(void* const* d_in, const int* in_sizes, int n_in,
                              void* d_out, int out_size) {
    const int*   word_seq   = (const int*)  d_in[0];
    const int*   chars      = (const int*)  d_in[1];
    const int*   char_lens  = (const int*)  d_in[2];
    const int*   feat_seq   = (const int*)  d_in[3];
    const float* char_emb   = (const float*)d_in[4];
    const float* word_emb   = (const float*)d_in[5];
    const float* prefix_emb = (const float*)d_in[6];
    const float* Wih_c = (const float*)d_in[7];
    const float* Whh_c = (const float*)d_in[8];
    const float* bih_c = (const float*)d_in[9];
    const float* bhh_c = (const float*)d_in[10];
    const float* Wih_f = (const float*)d_in[11];
    const float* Whh_f = (const float*)d_in[12];
    const float* bih_f = (const float*)d_in[13];
    const float* bhh_f = (const float*)d_in[14];
    const float* Wih_b = (const float*)d_in[15];
    const float* Whh_b = (const float*)d_in[16];
    const float* bih_b = (const float*)d_in[17];
    const float* bhh_b = (const float*)d_in[18];
    const float* Wpos  = (const float*)d_in[19];
    const float* bpos  = (const float*)d_in[20];
    const float* Wner  = (const float*)d_in[21];
    const float* bner  = (const float*)d_in[22];
    float* out = (float*)d_out;

    float *p_hA, *p_hB, *p_wc, *p_xgf, *p_xgb;
    __nv_bfloat16 *p_xc16h, *p_xc16l, *p_h16hA, *p_h16lA, *p_h16hB, *p_h16lB;
    cudaGetSymbolAddress((void**)&p_hA,  g_hA);
    cudaGetSymbolAddress((void**)&p_hB,  g_hB);
    cudaGetSymbolAddress((void**)&p_wc,  g_wc);
    cudaGetSymbolAddress((void**)&p_xgf, g_xgf);
    cudaGetSymbolAddress((void**)&p_xgb, g_xgb);
    cudaGetSymbolAddress((void**)&p_xc16h, g_xc16h);
    cudaGetSymbolAddress((void**)&p_xc16l, g_xc16l);
    cudaGetSymbolAddress((void**)&p_h16hA, g_h16hA);
    cudaGetSymbolAddress((void**)&p_h16lA, g_h16lA);
    cudaGetSymbolAddress((void**)&p_h16hB, g_h16hB);
    cudaGetSymbolAddress((void**)&p_h16lB, g_h16lB);

    cudaFuncSetAttribute(k_char_mma, cudaFuncAttributeMaxDynamicSharedMemorySize,
                         SMEM_MMA_BYTES);

    // launches 1-3: sort, fused prep (weights+bias+h0/c0), gather
    k_sort<<<1, 256>>>(char_lens);
    k_prep_all<<<5120 + 8 + 8192, 256>>>(Wih_c, Whh_c, bih_c, bhh_c,
                                         feat_seq, prefix_emb);
    k_fix_h0<<<(S * 512) / 256, 256>>>(feat_seq, prefix_emb);
    k_gather_xc<<<(L * S * 64) / 256, 256>>>(chars, char_emb);

    // char LSTM: 16 mma.sync steps, h ping-pong (fp32 + bf16 hi/lo), early-exit
    dim3 gridC(G4H / 128, S / 128);
    for (int t = 0; t < L; ++t) {
        __nv_bfloat16* hch = (t & 1) ? p_h16hB : p_h16hA;
        __nv_bfloat16* hcl = (t & 1) ? p_h16lB : p_h16lA;
        __nv_bfloat16* hnh = (t & 1) ? p_h16hA : p_h16hB;
        __nv_bfloat16* hnl = (t & 1) ? p_h16lA : p_h16lB;
        float*         hnf = (t & 1) ? p_hA    : p_hB;
        k_char_mma<<<gridC, 256, SMEM_MMA_BYTES>>>(
            p_xc16h + (size_t)t * S * EC, p_xc16l + (size_t)t * S * EC,
            hch, hcl, hnh, hnl, hnf, t);
    }

    // word LSTM input + merged x-gate precompute (fwd+bwd in one launch)
    k_build_wc<<<(S * 256) / 256, 256>>>(word_seq, word_emb);
    dim3 gridX(G4HH / 128, S / 128, 2);
    gemm_xg<<<gridX, 256>>>(p_wc, Wih_f, Wih_b,
                            bih_f, bhh_f, bih_b, bhh_b,
                            p_xgf, p_xgb);

    // sequential bi-LSTM recurrence (2 clusters of 8 CTAs, fwd + bwd concurrent)
    k_word_lstm<<<16, 512>>>(Whh_f, Whh_b);

    // output heads
    k_logits<<<S, NPOS>>>(Wpos, bpos, out, NPOS);
    k_logits<<<S, NNER>>>(Wner, bner, out + (size_t)S * NPOS, NNER);

    (void)in_sizes; (void)n_in; (void)out_size;
}

// round 14
// speedup vs baseline: 1.3035x; 1.0411x over previous
#include <cuda_runtime.h>
#include <cuda_bf16.h>
#include <cstdint>
#include <cstddef>
#include <math.h>

#define S    4096
#define L    16
#define H    512
#define EC   128
#define EW   512
#define HH   256
#define G4H  2048   // 4*H
#define G4HH 1024   // 4*HH
#define NPOS 64
#define NNER 32
#define KCAT 640    // EC + H

typedef unsigned long long ull;

// ---------------- scratch (device globals; no dynamic allocation) ----------------
__device__ __nv_bfloat16 g_xc16h[(size_t)L * S * EC];  // char embeddings bf16-hi
__device__ __nv_bfloat16 g_xc16l[(size_t)L * S * EC];  // bf16-lo
__device__ __nv_bfloat16 g_h16hA[(size_t)S * H];       // h bf16-hi ping
__device__ __nv_bfloat16 g_h16lA[(size_t)S * H];       // h bf16-lo ping
__device__ __nv_bfloat16 g_h16hB[(size_t)S * H];       // h bf16-hi pong
__device__ __nv_bfloat16 g_h16lB[(size_t)S * H];       // h bf16-lo pong
__device__ __nv_bfloat16 g_w16h[(size_t)G4H * KCAT];   // permuted Wcat bf16-hi
__device__ __nv_bfloat16 g_w16l[(size_t)G4H * KCAT];   // permuted Wcat bf16-lo
__device__ float g_hA[(size_t)S * H];          // char LSTM hidden fp32 ping
__device__ float g_hB[(size_t)S * H];          // char LSTM hidden fp32 pong
__device__ float g_c [(size_t)S * H];          // char LSTM cell (sorted order)
__device__ float g_wc [(size_t)S * (EW + H)];  // word LSTM input [S,1024] (orig order)
__device__ float g_xgf[(size_t)S * G4HH];      // precomputed x-gates fwd
__device__ float g_xgb[(size_t)S * G4HH];      // precomputed x-gates bwd
__device__ float g_out[(size_t)S * H];         // bi-LSTM output [S,512]
__device__ float g_biasP[G4H];                 // permuted bih_c+bhh_c
__device__ int   g_perm[S];                    // sorted slot -> original index
__device__ int   g_inv[S];                     // original index -> sorted slot
__device__ int   g_lensS[S];                   // lens in sorted order (descending)
__device__ int   g_cnt[L];                     // cnt[t] = #words with len > t

// fast transcendentals (err ~1e-7 rel; tolerance is 1e-3)
__device__ __forceinline__ float fsig(float x) {
    return __fdividef(1.f, 1.f + __expf(-x));
}
__device__ __forceinline__ float ftanh(float x) {
    return 1.f - __fdividef(2.f, __expf(2.f * x) + 1.f);
}

__device__ __forceinline__ ull pack2(float x, float y) {
    ull r; asm("mov.b64 %0,{%1,%2};" : "=l"(r) : "f"(x), "f"(y)); return r;
}
__device__ __forceinline__ void unpack2(ull v, float& x, float& y) {
    asm("mov.b64 {%0,%1},%2;" : "=f"(x), "=f"(y) : "l"(v));
}
__device__ __forceinline__ ull ffma2(ull a, ull b, ull c) {
    ull d; asm("fma.rn.f32x2 %0,%1,%2,%3;" : "=l"(d) : "l"(a), "l"(b), "l"(c)); return d;
}

#define SMEM_SWIZZLE_128B(bo) ((bo) ^ (((bo) >> 3) & 0x70))

// ---------------- counting sort by char length (descending) ----------------
__global__ void k_sort(const int* __restrict__ lens) {
    __shared__ int hist[17], off[17];
    int tid = threadIdx.x;
    if (tid < 17) hist[tid] = 0;
    __syncthreads();
    for (int s = tid; s < S; s += blockDim.x) atomicAdd(&hist[lens[s]], 1);
    __syncthreads();
    if (tid == 0) {
        int acc = 0;
        for (int l = 16; l >= 1; --l) { off[l] = acc; acc += hist[l]; }
        for (int t = 0; t < L; ++t) g_cnt[t] = off[t + 1] + hist[t + 1];
    }
    __syncthreads();
    for (int s = tid; s < S; s += blockDim.x) {
        int l = lens[s];
        int pos = atomicAdd(&off[l], 1);
        g_perm[pos] = s;
        g_inv[s] = pos;
        g_lensS[pos] = l;
    }
}

// ---------------- fused prep: bf16 weights + bias + h/c init -----------------
__global__ void k_prep_all(const float* __restrict__ Wih_c,
                           const float* __restrict__ Whh_c,
                           const float* __restrict__ bih_c,
                           const float* __restrict__ bhh_c,
                           const int*   __restrict__ feat_seq,
                           const float* __restrict__ prefix_emb) {
    int b = blockIdx.x;
    if (b < 5120) {
        int idx = b * 256 + threadIdx.x;               // < 2048*640
        int n = idx / KCAT, k = idx % KCAT;
        int jh = n >> 2, g = n & 3;
        int row = g * H + jh;
        float w = (k < EC) ? Wih_c[(size_t)row * EC + k]
                           : Whh_c[(size_t)row * H + (k - EC)];
        __nv_bfloat16 hi = __float2bfloat16(w);
        g_w16h[idx] = hi;
        g_w16l[idx] = __float2bfloat16(w - __bfloat162float(hi));
    } else if (b < 5128) {
        int n = (b - 5120) * 256 + threadIdx.x;        // < 2048
        int jh = n >> 2, g = n & 3;
        int row = g * H + jh;
        g_biasP[n] = bih_c[row] + bhh_c[row];
    } else {
        int idx = (b - 5128) * 256 + threadIdx.x;      // < S*512
        int j = idx & 511;
        int slot = idx >> 9;
        int s = g_perm[slot];
        float h0 = prefix_emb[(size_t)feat_seq[s] * H + j];
        g_hA[idx] = h0;
        __nv_bfloat16 hi = __float2bfloat16(h0);
        g_h16hA[idx] = hi;
        g_h16lA[idx] = __float2bfloat16(h0 - __bfloat162float(hi));
        g_c[idx] = 0.f;
    }
}

// ---------------- embedding gather: char emb -> bf16 hi/lo (sorted order) -------
__global__ void k_gather_xc(const int* __restrict__ chars,
                            const float* __restrict__ char_emb) {
    int idx = blockIdx.x * blockDim.x + threadIdx.x;   // < L*S*64 (pairs)
    int e2 = idx & 63;
    int slot = (idx >> 6) & (S - 1);
    int t = idx >> 18;
    int s = g_perm[slot];
    float2 v = *reinterpret_cast<const float2*>(
        char_emb + (size_t)chars[s * L + t] * EC + e2 * 2);
    __nv_bfloat16 h0 = __float2bfloat16(v.x), h1 = __float2bfloat16(v.y);
    __nv_bfloat16 l0 = __float2bfloat16(v.x - __bfloat162float(h0));
    __nv_bfloat16 l1 = __float2bfloat16(v.y - __bfloat162float(h1));
    reinterpret_cast<__nv_bfloat162*>(g_xc16h)[idx] = __nv_bfloat162(h0, h1);
    reinterpret_cast<__nv_bfloat162*>(g_xc16l)[idx] = __nv_bfloat162(l0, l1);
}

__global__ void k_build_wc(const int* __restrict__ word_seq,
                           const float* __restrict__ word_emb) {
    int idx = blockIdx.x * blockDim.x + threadIdx.x;   // < S*256
    int k4 = idx & 255;
    int s = idx >> 8;
    float4 v;
    if (k4 < 128) {
        v = reinterpret_cast<const float4*>(word_emb)[(size_t)word_seq[s] * 128 + k4];
    } else {
        int slot = g_inv[s];
        int len = g_lensS[slot];
        const float4* hp = reinterpret_cast<const float4*>((len & 1) ? g_hB : g_hA);
        v = hp[(size_t)slot * 128 + (k4 - 128)];
    }
    reinterpret_cast<float4*>(g_wc)[idx] = v;
}

// ---------------- char-LSTM step via mma.sync bf16 (split hi/lo) + cell --------
// 128(M)x128(N) CTA tile; K'' = 1920 bf16 across 3 split passes
// (blk0: Ah*Bh, blk1: Ah*Bl, blk2: Al*Bh). 30 stages of K=64, 2-stage
// cp.async pipeline into SW128-swizzled smem; ldmatrix + mma.m16n8k16.
// 8 warps = 2(m) x 4(n); warp tile m64 x n32. Epilogue via padded smem.
#define SM_BIAS 0
#define SM_A(b) (1024 + (b) * 16384)
#define SM_B(b) (33792 + (b) * 16384)
#define SM_G    1024
#define GPITCH  132
#define SMEM_MMA_BYTES (1024 + 128 * GPITCH * 4 + 1024)

#define CPA16(dst, src) \
    asm volatile("cp.async.cg.shared.global [%0], [%1], 16;" \
                 :: "r"(dst), "l"(src) : "memory")
#define CPA_COMMIT() asm volatile("cp.async.commit_group;" ::: "memory")
#define CPA_WAIT(n)  asm volatile("cp.async.wait_group %0;" :: "n"(n) : "memory")

__global__ __launch_bounds__(256)
void k_char_mma(const __nv_bfloat16* __restrict__ xh,
                const __nv_bfloat16* __restrict__ xl,
                const __nv_bfloat16* __restrict__ hch,
                const __nv_bfloat16* __restrict__ hcl,
                __nv_bfloat16* __restrict__ hnh,
                __nv_bfloat16* __restrict__ hnl,
                float* __restrict__ hnf,
                int t) {
    extern __shared__ char smem_raw[];
    const int cnt = g_cnt[t];
    const int m0 = blockIdx.y * 128;
    if (m0 >= cnt) return;
    const int n0 = blockIdx.x * 128;

    char* smem = reinterpret_cast<char*>(
        (((uintptr_t)smem_raw) + 1023) & ~(uintptr_t)1023);
    uint32_t sb = (uint32_t)__cvta_generic_to_shared(smem);

    const int tid = threadIdx.x;
    const int wid = tid >> 5, lane = tid & 31;
    float* sbias = reinterpret_cast<float*>(smem + SM_BIAS);
    if (tid < 128) sbias[tid] = g_biasP[n0 + tid];

    const int wm = wid >> 2;       // 0..1  (m block of 64)
    const int wn = wid & 3;        // 0..3  (n block of 32)

    float acc[4][4][4];
    #pragma unroll
    for (int i = 0; i < 4; i++)
        #pragma unroll
        for (int j = 0; j < 4; j++)
            #pragma unroll
            for (int k = 0; k < 4; k++) acc[i][j][k] = 0.f;

    // staging: each thread cp.asyncs 4x16B for A and 4x16B for B per stage
    const int lr = tid >> 3;            // 0..31 row group
    const int lc = tid & 7;             // 16B chunk within 128B row

    // ldmatrix fragment coordinates
    const int a_row = wm * 64 + ((lane >> 3) & 1) * 8 + (lane & 7);   // + mt*16
    const int a_kb  = (lane >> 4) * 16;                               // + ks*32
    const int b_row = wn * 32 + (lane & 7);                           // + nt*8
    const int b_kb  = ((lane >> 3) & 1) * 16;                         // + ks*32

    auto stage_load = [&](int s, int buf) {
        int kk0 = s * 64;
        int blk = kk0 / 640;
        int ko  = kk0 - blk * 640;
        const __nv_bfloat16* Ab;
        size_t astr;
        if (ko < EC) { Ab = (blk < 2 ? xh : xl) + ko; astr = EC; }
        else         { Ab = (blk < 2 ? hch : hcl) + (ko - EC); astr = H; }
        const __nv_bfloat16* Bb = (blk == 1 ? g_w16l : g_w16h) + ko;
        uint32_t sa = sb + SM_A(buf);
        uint32_t sbm = sb + SM_B(buf);
        #pragma unroll
        for (int p = 0; p < 4; ++p) {
            int r = p * 32 + lr;
            uint32_t so = SMEM_SWIZZLE_128B((uint32_t)(r * 128 + lc * 16));
            CPA16(sa + so,  Ab + (size_t)(m0 + r) * astr + lc * 8);
            CPA16(sbm + so, Bb + (size_t)(n0 + r) * KCAT + lc * 8);
        }
    };

    stage_load(0, 0);
    CPA_COMMIT();

    for (int s = 0; s < 30; ++s) {
        int buf = s & 1;
        if (s + 1 < 30) {
            stage_load(s + 1, buf ^ 1);
            CPA_COMMIT();
            CPA_WAIT(1);
        } else {
            CPA_WAIT(0);
        }
        __syncthreads();

        #pragma unroll
        for (int ks = 0; ks < 4; ++ks) {
            uint32_t afr[4][4];
            #pragma unroll
            for (int mt = 0; mt < 4; ++mt) {
                uint32_t ad = sb + SM_A(buf) + SMEM_SWIZZLE_128B(
                    (uint32_t)((a_row + mt * 16) * 128 + ks * 32 + a_kb));
                asm volatile("ldmatrix.sync.aligned.m8n8.x4.shared.b16 {%0,%1,%2,%3}, [%4];"
                             : "=r"(afr[mt][0]), "=r"(afr[mt][1]),
                               "=r"(afr[mt][2]), "=r"(afr[mt][3]) : "r"(ad));
            }
            uint32_t bfr[4][2];
            #pragma unroll
            for (int nt = 0; nt < 4; ++nt) {
                uint32_t bd = sb + SM_B(buf) + SMEM_SWIZZLE_128B(
                    (uint32_t)((b_row + nt * 8) * 128 + ks * 32 + b_kb));
                asm volatile("ldmatrix.sync.aligned.m8n8.x2.shared.b16 {%0,%1}, [%2];"
                             : "=r"(bfr[nt][0]), "=r"(bfr[nt][1]) : "r"(bd));
            }
            #pragma unroll
            for (int mt = 0; mt < 4; ++mt)
                #pragma unroll
                for (int nt = 0; nt < 4; ++nt) {
                    asm volatile(
                        "mma.sync.aligned.m16n8k16.row.col.f32.bf16.bf16.f32 "
                        "{%0,%1,%2,%3}, {%4,%5,%6,%7}, {%8,%9}, {%0,%1,%2,%3};"
                        : "+f"(acc[mt][nt][0]), "+f"(acc[mt][nt][1]),
                          "+f"(acc[mt][nt][2]), "+f"(acc[mt][nt][3])
                        : "r"(afr[mt][0]), "r"(afr[mt][1]),
                          "r"(afr[mt][2]), "r"(afr[mt][3]),
                          "r"(bfr[nt][0]), "r"(bfr[nt][1]));
                }
        }
        __syncthreads();
    }

    // accumulators -> padded smem gates buffer
    float* gsm = reinterpret_cast<float*>(smem + SM_G);
    {
        int gr = lane >> 2;            // 0..7
        int gc0 = 2 * (lane & 3);
        #pragma unroll
        for (int mt = 0; mt < 4; ++mt)
            #pragma unroll
            for (int nt = 0; nt < 4; ++nt) {
                int r0 = wm * 64 + mt * 16 + gr;
                int c  = wn * 32 + nt * 8 + gc0;
                gsm[r0 * GPITCH + c]       = acc[mt][nt][0];
                gsm[r0 * GPITCH + c + 1]   = acc[mt][nt][1];
                gsm[(r0 + 8) * GPITCH + c]     = acc[mt][nt][2];
                gsm[(r0 + 8) * GPITCH + c + 1] = acc[mt][nt][3];
            }
    }
    __syncthreads();

    // fused LSTM cell update: 2 threads per row, 16 units each
    {
        int r = tid >> 1, half = tid & 1;
        int m = m0 + r;
        if (t < g_lensS[m]) {
            const float* grow = gsm + r * GPITCH + half * 64;
            const float* brow = sbias + half * 64;
            size_t ci = (size_t)m * H + (n0 >> 2) + half * 16;
            #pragma unroll
            for (int u = 0; u < 16; ++u) {
                float iv = grow[4 * u + 0] + brow[4 * u + 0];
                float fv = grow[4 * u + 1] + brow[4 * u + 1];
                float gv = grow[4 * u + 2] + brow[4 * u + 2];
                float ov = grow[4 * u + 3] + brow[4 * u + 3];
                float cc = g_c[ci + u];
                cc = fsig(fv) * cc + fsig(iv) * ftanh(gv);
                g_c[ci + u] = cc;
                float hh = fsig(ov) * ftanh(cc);
                hnf[ci + u] = hh;
                __nv_bfloat16 hb16 = __float2bfloat16(hh);
                hnh[ci + u] = hb16;
                hnl[ci + u] = __float2bfloat16(hh - __bfloat162float(hb16));
            }
        }
    }
}

// ---------------- merged x-gate GEMM (fwd + bwd via blockIdx.z) ----------------
__global__ __launch_bounds__(256)
void gemm_xg(const float* __restrict__ A1,
             const float* __restrict__ Bf, const float* __restrict__ Bb,
             const float* __restrict__ b1f, const float* __restrict__ b2f,
             const float* __restrict__ b1b, const float* __restrict__ b2b,
             float* __restrict__ Cf, float* __restrict__ Cb) {
    const int K1 = EW + H, N = G4HH;
    const int BM = 128, BN = 128, BK = 8;
    const float* B1 = blockIdx.z ? Bb : Bf;
    const float* b1 = blockIdx.z ? b1b : b1f;
    const float* b2 = blockIdx.z ? b2b : b2f;
    float* C = blockIdx.z ? Cb : Cf;

    __shared__ __align__(16) float As[BK][BM];
    __shared__ __align__(16) float Bs[BK][BN];
    int tid = threadIdx.x;
    int m0 = blockIdx.y * BM;
    int n0 = blockIdx.x * BN;
    int aRow = tid >> 1, aCol = (tid & 1) * 4;
    int tx = tid & 15, ty = tid >> 4;

    ull acc2[8][4];
    #pragma unroll
    for (int i = 0; i < 8; i++)
        #pragma unroll
        for (int j = 0; j < 4; j++) acc2[i][j] = 0ULL;

    for (int kt = 0; kt < K1; kt += BK) {
        int k = kt + aCol;
        {
            float4 v = *reinterpret_cast<const float4*>(A1 + (size_t)(m0 + aRow) * K1 + k);
            As[aCol + 0][aRow] = v.x; As[aCol + 1][aRow] = v.y;
            As[aCol + 2][aRow] = v.z; As[aCol + 3][aRow] = v.w;
        }
        {
            float4 v = *reinterpret_cast<const float4*>(B1 + (size_t)(n0 + aRow) * K1 + k);
            Bs[aCol + 0][aRow] = v.x; Bs[aCol + 1][aRow] = v.y;
            Bs[aCol + 2][aRow] = v.z; Bs[aCol + 3][aRow] = v.w;
        }
        __syncthreads();
        #pragma unroll
        for (int kk = 0; kk < BK; kk++) {
            float a[8];
            *reinterpret_cast<float4*>(&a[0]) = *reinterpret_cast<const float4*>(&As[kk][ty * 8]);
            *reinterpret_cast<float4*>(&a[4]) = *reinterpret_cast<const float4*>(&As[kk][ty * 8 + 4]);
            ull b2r[4];
            const ull* bp = reinterpret_cast<const ull*>(&Bs[kk][tx * 8]);
            b2r[0] = bp[0]; b2r[1] = bp[1]; b2r[2] = bp[2]; b2r[3] = bp[3];
            #pragma unroll
            for (int i = 0; i < 8; i++) {
                ull ad = pack2(a[i], a[i]);
                #pragma unroll
                for (int j = 0; j < 4; j++)
                    acc2[i][j] = ffma2(ad, b2r[j], acc2[i][j]);
            }
        }
        __syncthreads();
    }
    #pragma unroll
    for (int i = 0; i < 8; i++) {
        int m = m0 + ty * 8 + i;
        #pragma unroll
        for (int jj = 0; jj < 4; jj++) {
            float lo, hi;
            unpack2(acc2[i][jj], lo, hi);
            int n = n0 + tx * 8 + jj * 2;
            C[(size_t)m * N + n]     = lo + b1[n] + b2[n];
            C[(size_t)m * N + n + 1] = hi + b1[n + 1] + b2[n + 1];
        }
    }
}

// ---------------- word bi-LSTM recurrence: 2 clusters of 8 CTAs, 512 thr ----------
__global__ void __cluster_dims__(8, 1, 1) __launch_bounds__(512, 1)
k_word_lstm(const float* __restrict__ Whh_f, const float* __restrict__ Whh_b) {
    __shared__ __align__(16) float hb[2][HH];
    __shared__ float partial[512];

    unsigned rank;
    asm("mov.u32 %0, %%cluster_ctarank;" : "=r"(rank));
    int dir = blockIdx.x / 8;
    const float* Whh = dir ? Whh_b : Whh_f;
    const float* xg  = dir ? g_xgb : g_xgf;

    int tid = threadIdx.x;
    int p   = tid & 127;
    int q   = tid >> 7;
    int gte = p >> 5;
    int jj  = p & 31;
    int grow = gte * HH + (int)rank * 32 + jj;

    ull w2[32];
    const float4* wsrc = reinterpret_cast<const float4*>(Whh + (size_t)grow * HH + q * 64);
    #pragma unroll
    for (int i = 0; i < 16; i++) {
        float4 f = wsrc[i];
        w2[2 * i]     = pack2(f.x, f.y);
        w2[2 * i + 1] = pack2(f.z, f.w);
    }

    int lane = tid & 31;
    unsigned raA[8], raB[8];
    {
        unsigned loff0 = (unsigned)__cvta_generic_to_shared(&hb[0][rank * 32 + lane]);
        unsigned loff1 = (unsigned)__cvta_generic_to_shared(&hb[1][rank * 32 + lane]);
        #pragma unroll
        for (int peer = 0; peer < 8; ++peer) {
            asm("mapa.shared::cluster.u32 %0, %1, %2;" : "=r"(raA[peer]) : "r"(loff0), "r"(peer));
            asm("mapa.shared::cluster.u32 %0, %1, %2;" : "=r"(raB[peer]) : "r"(loff1), "r"(peer));
        }
    }

    if (tid < HH) hb[0][tid] = 0.f;
    __syncthreads();
    asm volatile("barrier.cluster.arrive.aligned;" ::: "memory");
    asm volatile("barrier.cluster.wait.aligned;"   ::: "memory");

    float c_reg = 0.f;
    int par = 0;
    const int xbase = (int)rank * 32 + lane;
    float xv0 = 0.f, xv1 = 0.f, xv2 = 0.f, xv3 = 0.f;
    if (tid < 32) {
        size_t r0 = (size_t)(dir ? (S - 1) : 0) * G4HH + xbase;
        xv0 = __ldg(&xg[r0]);       xv1 = __ldg(&xg[r0 + 256]);
        xv2 = __ldg(&xg[r0 + 512]); xv3 = __ldg(&xg[r0 + 768]);
    }

    for (int t = 0; t < S; ++t) {
        int row = dir ? (S - 1 - t) : t;

        const ull* hv = reinterpret_cast<const ull*>(&hb[par][q * 64]);
        ull a0 = 0ULL, a1 = 0ULL, a2 = 0ULL, a3 = 0ULL;
        #pragma unroll
        for (int i = 0; i < 32; i += 4) {
            a0 = ffma2(w2[i + 0], hv[i + 0], a0);
            a1 = ffma2(w2[i + 1], hv[i + 1], a1);
            a2 = ffma2(w2[i + 2], hv[i + 2], a2);
            a3 = ffma2(w2[i + 3], hv[i + 3], a3);
        }
        float l0, h0f, l1, h1f, l2, h2f, l3, h3f;
        unpack2(a0, l0, h0f); unpack2(a1, l1, h1f);
        unpack2(a2, l2, h2f); unpack2(a3, l3, h3f);
        partial[tid] = ((l0 + h0f) + (l1 + h1f)) + ((l2 + h2f) + (l3 + h3f));

        float nx0 = 0.f, nx1 = 0.f, nx2 = 0.f, nx3 = 0.f;
        if (tid < 32 && t + 1 < S) {
            int rn = dir ? (S - 2 - t) : (t + 1);
            size_t rb = (size_t)rn * G4HH + xbase;
            nx0 = __ldg(&xg[rb]);       nx1 = __ldg(&xg[rb + 256]);
            nx2 = __ldg(&xg[rb + 512]); nx3 = __ldg(&xg[rb + 768]);
        }
        __syncthreads();
        if (tid < 32) {
            float p0 = (partial[lane]       + partial[lane + 128])
                     + (partial[lane + 256] + partial[lane + 384]);
            float p1 = (partial[32 + lane]       + partial[32 + lane + 128])
                     + (partial[32 + lane + 256] + partial[32 + lane + 384]);
            float p2 = (partial[64 + lane]       + partial[64 + lane + 128])
                     + (partial[64 + lane + 256] + partial[64 + lane + 384]);
            float p3 = (partial[96 + lane]       + partial[96 + lane + 128])
                     + (partial[96 + lane + 256] + partial[96 + lane + 384]);
            float iv = fsig(p0 + xv0);
            float fv = fsig(p1 + xv1);
            float gg = ftanh(p2 + xv2);
            float ov = fsig(p3 + xv3);
            c_reg = fv * c_reg + iv * gg;
            float hnew = ov * ftanh(c_reg);
            g_out[(size_t)row * H + dir * HH + rank * 32 + lane] = hnew;
            if (par == 0) {
                #pragma unroll
                for (int peer = 0; peer < 8; ++peer)
                    asm volatile("st.shared::cluster.f32 [%0], %1;"
                                 :: "r"(raB[peer]), "f"(hnew) : "memory");
            } else {
                #pragma unroll
                for (int peer = 0; peer < 8; ++peer)
                    asm volatile("st.shared::cluster.f32 [%0], %1;"
                                 :: "r"(raA[peer]), "f"(hnew) : "memory");
            }
        }
        asm volatile("barrier.cluster.arrive.aligned;" ::: "memory");
        asm volatile("barrier.cluster.wait.aligned;"   ::: "memory");
        par ^= 1;
        xv0 = nx0; xv1 = nx1; xv2 = nx2; xv3 = nx3;
    }
}

// ---------------- output heads: logits + log_softmax ----------------
__global__ void k_logits(const float* __restrict__ W,   // [C,512]
                         const float* __restrict__ bias,
                         float* __restrict__ dst, int C) {
    __shared__ float row[H];
    __shared__ float red[64];
    int s = blockIdx.x, tid = threadIdx.x;
    for (int k = tid; k < H; k += blockDim.x) row[k] = g_out[(size_t)s * H + k];
    __syncthreads();
    float acc = bias[tid];
    const float4* w4 = reinterpret_cast<const float4*>(W + (size_t)tid * H);
    const float4* r4 = reinterpret_cast<const float4*>(row);
    #pragma unroll 8
    for (int q = 0; q < H / 4; q++) {
        float4 w = w4[q], r = r4[q];
        acc += w.x * r.x + w.y * r.y + w.z * r.z + w.w * r.w;
    }
    red[tid] = acc;
    __syncthreads();
    for (int off = C >> 1; off; off >>= 1) {
        if (tid < off) red[tid] = fmaxf(red[tid], red[tid + off]);
        __syncthreads();
    }
    float mx = red[0];
    __syncthreads();
    red[tid] = expf(acc - mx);
    __syncthreads();
    for (int off = C >> 1; off; off >>= 1) {
        if (tid < off) red[tid] += red[tid + off];
        __syncthreads();
    }
    float lse = mx + logf(red[0]);
    dst[(size_t)s * C + tid] = acc - lse;
}

// ---------------- launch ----------------
extern "C" void kernel_launch(void* const* d_in, const int* in_sizes, int n_in,
                              void* d_out, int out_size) {
    const int*   word_seq   = (const int*)  d_in[0];
    const int*   chars      = (const int*)  d_in[1];
    const int*   char_lens  = (const int*)  d_in[2];
    const int*   feat_seq   = (const int*)  d_in[3];
    const float* char_emb   = (const float*)d_in[4];
    const float* word_emb   = (const float*)d_in[5];
    const float* prefix_emb = (const float*)d_in[6];
    const float* Wih_c = (const float*)d_in[7];
    const float* Whh_c = (const float*)d_in[8];
    const float* bih_c = (const float*)d_in[9];
    const float* bhh_c = (const float*)d_in[10];
    const float* Wih_f = (const float*)d_in[11];
    const float* Whh_f = (const float*)d_in[12];
    const float* bih_f = (const float*)d_in[13];
    const float* bhh_f = (const float*)d_in[14];
    const float* Wih_b = (const float*)d_in[15];
    const float* Whh_b = (const float*)d_in[16];
    const float* bih_b = (const float*)d_in[17];
    const float* bhh_b = (const float*)d_in[18];
    const float* Wpos  = (const float*)d_in[19];
    const float* bpos  = (const float*)d_in[20];
    const float* Wner  = (const float*)d_in[21];
    const float* bner  = (const float*)d_in[22];
    float* out = (float*)d_out;

    float *p_hA, *p_hB, *p_wc, *p_xgf, *p_xgb;
    __nv_bfloat16 *p_xc16h, *p_xc16l, *p_h16hA, *p_h16lA, *p_h16hB, *p_h16lB;
    cudaGetSymbolAddress((void**)&p_hA,  g_hA);
    cudaGetSymbolAddress((void**)&p_hB,  g_hB);
    cudaGetSymbolAddress((void**)&p_wc,  g_wc);
    cudaGetSymbolAddress((void**)&p_xgf, g_xgf);
    cudaGetSymbolAddress((void**)&p_xgb, g_xgb);
    cudaGetSymbolAddress((void**)&p_xc16h, g_xc16h);
    cudaGetSymbolAddress((void**)&p_xc16l, g_xc16l);
    cudaGetSymbolAddress((void**)&p_h16hA, g_h16hA);
    cudaGetSymbolAddress((void**)&p_h16lA, g_h16lA);
    cudaGetSymbolAddress((void**)&p_h16hB, g_h16hB);
    cudaGetSymbolAddress((void**)&p_h16lB, g_h16lB);

    cudaFuncSetAttribute(k_char_mma, cudaFuncAttributeMaxDynamicSharedMemorySize,
                         SMEM_MMA_BYTES);

    // launches 1-3: sort, fused prep (weights+bias+h0/c0), gather
    k_sort<<<1, 256>>>(char_lens);
    k_prep_all<<<5120 + 8 + 8192, 256>>>(Wih_c, Whh_c, bih_c, bhh_c,
                                         feat_seq, prefix_emb);
    k_gather_xc<<<(L * S * 64) / 256, 256>>>(chars, char_emb);

    // char LSTM: 16 mma.sync steps (cp.async pipelined), h ping-pong, early-exit
    dim3 gridC(G4H / 128, S / 128);
    for (int t = 0; t < L; ++t) {
        __nv_bfloat16* hch = (t & 1) ? p_h16hB : p_h16hA;
        __nv_bfloat16* hcl = (t & 1) ? p_h16lB : p_h16lA;
        __nv_bfloat16* hnh = (t & 1) ? p_h16hA : p_h16hB;
        __nv_bfloat16* hnl = (t & 1) ? p_h16lA : p_h16lB;
        float*         hnf = (t & 1) ? p_hA    : p_hB;
        k_char_mma<<<gridC, 256, SMEM_MMA_BYTES>>>(
            p_xc16h + (size_t)t * S * EC, p_xc16l + (size_t)t * S * EC,
            hch, hcl, hnh, hnl, hnf, t);
    }

    // word LSTM input + merged x-gate precompute (fwd+bwd in one launch)
    k_build_wc<<<(S * 256) / 256, 256>>>(word_seq, word_emb);
    dim3 gridX(G4HH / 128, S / 128, 2);
    gemm_xg<<<gridX, 256>>>(p_wc, Wih_f, Wih_b,
                            bih_f, bhh_f, bih_b, bhh_b,
                            p_xgf, p_xgb);

    // sequential bi-LSTM recurrence (2 clusters of 8 CTAs, fwd + bwd concurrent)
    k_word_lstm<<<16, 512>>>(Whh_f, Whh_b);

    // output heads
    k_logits<<<S, NPOS>>>(Wpos, bpos, out, NPOS);
    k_logits<<<S, NNER>>>(Wner, bner, out + (size_t)S * NPOS, NNER);

    (void)in_sizes; (void)n_in; (void)out_size;
}

// round 15
// speedup vs baseline: 1.3706x; 1.0514x over previous
#include <cuda_runtime.h>
#include <cuda_bf16.h>
#include <cstdint>
#include <cstddef>
#include <math.h>

#define S    4096
#define L    16
#define H    512
#define EC   128
#define EW   512
#define HH   256
#define G4H  2048   // 4*H
#define G4HH 1024   // 4*HH
#define NPOS 64
#define NNER 32
#define KCAT 640    // EC + H

typedef unsigned long long ull;

// ---------------- scratch (device globals; no dynamic allocation) ----------------
__device__ __nv_bfloat16 g_xc16h[(size_t)L * S * EC];  // char embeddings bf16-hi
__device__ __nv_bfloat16 g_xc16l[(size_t)L * S * EC];  // bf16-lo
__device__ __nv_bfloat16 g_h16hA[(size_t)S * H];       // h bf16-hi ping
__device__ __nv_bfloat16 g_h16lA[(size_t)S * H];       // h bf16-lo ping
__device__ __nv_bfloat16 g_h16hB[(size_t)S * H];       // h bf16-hi pong
__device__ __nv_bfloat16 g_h16lB[(size_t)S * H];       // h bf16-lo pong
__device__ __nv_bfloat16 g_w16h[(size_t)G4H * KCAT];   // permuted Wcat bf16-hi
__device__ __nv_bfloat16 g_w16l[(size_t)G4H * KCAT];   // permuted Wcat bf16-lo
__device__ __nv_bfloat16 g_wch[(size_t)S * G4HH];      // wc bf16-hi [S,1024]
__device__ __nv_bfloat16 g_wcl[(size_t)S * G4HH];      // wc bf16-lo
__device__ __nv_bfloat16 g_wf16h[(size_t)G4HH * G4HH]; // Wih_f bf16-hi [1024,1024]
__device__ __nv_bfloat16 g_wf16l[(size_t)G4HH * G4HH];
__device__ __nv_bfloat16 g_wb16h[(size_t)G4HH * G4HH]; // Wih_b bf16-hi
__device__ __nv_bfloat16 g_wb16l[(size_t)G4HH * G4HH];
__device__ float g_bxf[G4HH];                  // bih_f+bhh_f
__device__ float g_bxb[G4HH];                  // bih_b+bhh_b
__device__ float g_hA[(size_t)S * H];          // char LSTM hidden fp32 ping
__device__ float g_hB[(size_t)S * H];          // char LSTM hidden fp32 pong
__device__ float g_c [(size_t)S * H];          // char LSTM cell (sorted order)
__device__ float g_xgf[(size_t)S * G4HH];      // precomputed x-gates fwd
__device__ float g_xgb[(size_t)S * G4HH];      // precomputed x-gates bwd
__device__ float g_out[(size_t)S * H];         // bi-LSTM output [S,512]
__device__ float g_biasP[G4H];                 // permuted bih_c+bhh_c
__device__ int   g_perm[S];                    // sorted slot -> original index
__device__ int   g_inv[S];                     // original index -> sorted slot
__device__ int   g_lensS[S];                   // lens in sorted order (descending)
__device__ int   g_cnt[L];                     // cnt[t] = #words with len > t

// fast transcendentals (err ~1e-7 rel; tolerance is 1e-3)
__device__ __forceinline__ float fsig(float x) {
    return __fdividef(1.f, 1.f + __expf(-x));
}
__device__ __forceinline__ float ftanh(float x) {
    return 1.f - __fdividef(2.f, __expf(2.f * x) + 1.f);
}

__device__ __forceinline__ ull pack2(float x, float y) {
    ull r; asm("mov.b64 %0,{%1,%2};" : "=l"(r) : "f"(x), "f"(y)); return r;
}
__device__ __forceinline__ void unpack2(ull v, float& x, float& y) {
    asm("mov.b64 {%0,%1},%2;" : "=f"(x), "=f"(y) : "l"(v));
}
__device__ __forceinline__ ull ffma2(ull a, ull b, ull c) {
    ull d; asm("fma.rn.f32x2 %0,%1,%2,%3;" : "=l"(d) : "l"(a), "l"(b), "l"(c)); return d;
}

#define SMEM_SWIZZLE_128B(bo) ((bo) ^ (((bo) >> 3) & 0x70))

// ---------------- counting sort by char length (descending) ----------------
__global__ void k_sort(const int* __restrict__ lens) {
    __shared__ int hist[17], off[17];
    int tid = threadIdx.x;
    if (tid < 17) hist[tid] = 0;
    __syncthreads();
    for (int s = tid; s < S; s += blockDim.x) atomicAdd(&hist[lens[s]], 1);
    __syncthreads();
    if (tid == 0) {
        int acc = 0;
        for (int l = 16; l >= 1; --l) { off[l] = acc; acc += hist[l]; }
        for (int t = 0; t < L; ++t) g_cnt[t] = off[t + 1] + hist[t + 1];
    }
    __syncthreads();
    for (int s = tid; s < S; s += blockDim.x) {
        int l = lens[s];
        int pos = atomicAdd(&off[l], 1);
        g_perm[pos] = s;
        g_inv[s] = pos;
        g_lensS[pos] = l;
    }
}

// ---------------- fused prep: bf16 char weights + bias + h/c init ----------------
__global__ void k_prep_all(const float* __restrict__ Wih_c,
                           const float* __restrict__ Whh_c,
                           const float* __restrict__ bih_c,
                           const float* __restrict__ bhh_c,
                           const int*   __restrict__ feat_seq,
                           const float* __restrict__ prefix_emb) {
    int b = blockIdx.x;
    if (b < 5120) {
        int idx = b * 256 + threadIdx.x;               // < 2048*640
        int n = idx / KCAT, k = idx % KCAT;
        int jh = n >> 2, g = n & 3;
        int row = g * H + jh;
        float w = (k < EC) ? Wih_c[(size_t)row * EC + k]
                           : Whh_c[(size_t)row * H + (k - EC)];
        __nv_bfloat16 hi = __float2bfloat16(w);
        g_w16h[idx] = hi;
        g_w16l[idx] = __float2bfloat16(w - __bfloat162float(hi));
    } else if (b < 5128) {
        int n = (b - 5120) * 256 + threadIdx.x;        // < 2048
        int jh = n >> 2, g = n & 3;
        int row = g * H + jh;
        g_biasP[n] = bih_c[row] + bhh_c[row];
    } else {
        int idx = (b - 5128) * 256 + threadIdx.x;      // < S*512
        int j = idx & 511;
        int slot = idx >> 9;
        int s = g_perm[slot];
        float h0 = prefix_emb[(size_t)feat_seq[s] * H + j];
        g_hA[idx] = h0;
        __nv_bfloat16 hi = __float2bfloat16(h0);
        g_h16hA[idx] = hi;
        g_h16lA[idx] = __float2bfloat16(h0 - __bfloat162float(hi));
        g_c[idx] = 0.f;
    }
}

// ---------------- prep x-gate weights: Wih_f/b -> bf16 hi/lo, biases ------------
__global__ void k_prep_xg(const float* __restrict__ Wih_f,
                          const float* __restrict__ Wih_b,
                          const float* __restrict__ b1f, const float* __restrict__ b2f,
                          const float* __restrict__ b1b, const float* __restrict__ b2b) {
    int b = blockIdx.x;
    if (b < 4096) {
        int idx = b * 256 + threadIdx.x;               // < 1024*1024
        float w = Wih_f[idx];
        __nv_bfloat16 hi = __float2bfloat16(w);
        g_wf16h[idx] = hi;
        g_wf16l[idx] = __float2bfloat16(w - __bfloat162float(hi));
    } else if (b < 8192) {
        int idx = (b - 4096) * 256 + threadIdx.x;
        float w = Wih_b[idx];
        __nv_bfloat16 hi = __float2bfloat16(w);
        g_wb16h[idx] = hi;
        g_wb16l[idx] = __float2bfloat16(w - __bfloat162float(hi));
    } else if (b < 8196) {
        int n = (b - 8192) * 256 + threadIdx.x;        // < 1024
        g_bxf[n] = b1f[n] + b2f[n];
    } else {
        int n = (b - 8196) * 256 + threadIdx.x;
        g_bxb[n] = b1b[n] + b2b[n];
    }
}

// ---------------- embedding gather: char emb -> bf16 hi/lo (sorted order) -------
__global__ void k_gather_xc(const int* __restrict__ chars,
                            const float* __restrict__ char_emb) {
    int idx = blockIdx.x * blockDim.x + threadIdx.x;   // < L*S*64 (pairs)
    int e2 = idx & 63;
    int slot = (idx >> 6) & (S - 1);
    int t = idx >> 18;
    int s = g_perm[slot];
    float2 v = *reinterpret_cast<const float2*>(
        char_emb + (size_t)chars[s * L + t] * EC + e2 * 2);
    __nv_bfloat16 h0 = __float2bfloat16(v.x), h1 = __float2bfloat16(v.y);
    __nv_bfloat16 l0 = __float2bfloat16(v.x - __bfloat162float(h0));
    __nv_bfloat16 l1 = __float2bfloat16(v.y - __bfloat162float(h1));
    reinterpret_cast<__nv_bfloat162*>(g_xc16h)[idx] = __nv_bfloat162(h0, h1);
    reinterpret_cast<__nv_bfloat162*>(g_xc16l)[idx] = __nv_bfloat162(l0, l1);
}

// ---------------- word LSTM input -> bf16 hi/lo directly ----------------
__global__ void k_build_wc16(const int* __restrict__ word_seq,
                             const float* __restrict__ word_emb) {
    int idx = blockIdx.x * blockDim.x + threadIdx.x;   // < S*512 (pairs)
    int k2 = idx & 511;
    int s = idx >> 9;
    float2 v;
    if (k2 < 256) {
        v = reinterpret_cast<const float2*>(word_emb)[(size_t)word_seq[s] * 256 + k2];
    } else {
        int slot = g_inv[s];
        int len = g_lensS[slot];
        const float2* hp = reinterpret_cast<const float2*>((len & 1) ? g_hB : g_hA);
        v = hp[(size_t)slot * 256 + (k2 - 256)];
    }
    __nv_bfloat16 h0 = __float2bfloat16(v.x), h1 = __float2bfloat16(v.y);
    __nv_bfloat16 l0 = __float2bfloat16(v.x - __bfloat162float(h0));
    __nv_bfloat16 l1 = __float2bfloat16(v.y - __bfloat162float(h1));
    reinterpret_cast<__nv_bfloat162*>(g_wch)[idx] = __nv_bfloat162(h0, h1);
    reinterpret_cast<__nv_bfloat162*>(g_wcl)[idx] = __nv_bfloat162(l0, l1);
}

// ---------------- shared HMMA machinery ----------------
#define SM_BIAS 0
#define SM_A(b) (1024 + (b) * 16384)
#define SM_B(b) (33792 + (b) * 16384)
#define SM_G    1024
#define GPITCH  132
#define SMEM_MMA_BYTES (1024 + 128 * GPITCH * 4 + 1024)

#define CPA16(dst, src) \
    asm volatile("cp.async.cg.shared.global [%0], [%1], 16;" \
                 :: "r"(dst), "l"(src) : "memory")
#define CPA_COMMIT() asm volatile("cp.async.commit_group;" ::: "memory")
#define CPA_WAIT(n)  asm volatile("cp.async.wait_group %0;" :: "n"(n) : "memory")

// ---------------- char-LSTM step via mma.sync bf16 (split hi/lo) + cell --------
__global__ __launch_bounds__(256)
void k_char_mma(const __nv_bfloat16* __restrict__ xh,
                const __nv_bfloat16* __restrict__ xl,
                const __nv_bfloat16* __restrict__ hch,
                const __nv_bfloat16* __restrict__ hcl,
                __nv_bfloat16* __restrict__ hnh,
                __nv_bfloat16* __restrict__ hnl,
                float* __restrict__ hnf,
                int t) {
    extern __shared__ char smem_raw[];
    const int cnt = g_cnt[t];
    const int m0 = blockIdx.y * 128;
    if (m0 >= cnt) return;
    const int n0 = blockIdx.x * 128;

    char* smem = reinterpret_cast<char*>(
        (((uintptr_t)smem_raw) + 1023) & ~(uintptr_t)1023);
    uint32_t sb = (uint32_t)__cvta_generic_to_shared(smem);

    const int tid = threadIdx.x;
    const int wid = tid >> 5, lane = tid & 31;
    float* sbias = reinterpret_cast<float*>(smem + SM_BIAS);
    if (tid < 128) sbias[tid] = g_biasP[n0 + tid];

    const int wm = wid >> 2;
    const int wn = wid & 3;

    float acc[4][4][4];
    #pragma unroll
    for (int i = 0; i < 4; i++)
        #pragma unroll
        for (int j = 0; j < 4; j++)
            #pragma unroll
            for (int k = 0; k < 4; k++) acc[i][j][k] = 0.f;

    const int lr = tid >> 3;
    const int lc = tid & 7;
    const int a_row = wm * 64 + ((lane >> 3) & 1) * 8 + (lane & 7);
    const int a_kb  = (lane >> 4) * 16;
    const int b_row = wn * 32 + (lane & 7);
    const int b_kb  = ((lane >> 3) & 1) * 16;

    auto stage_load = [&](int s, int buf) {
        int kk0 = s * 64;
        int blk = kk0 / 640;
        int ko  = kk0 - blk * 640;
        const __nv_bfloat16* Ab;
        size_t astr;
        if (ko < EC) { Ab = (blk < 2 ? xh : xl) + ko; astr = EC; }
        else         { Ab = (blk < 2 ? hch : hcl) + (ko - EC); astr = H; }
        const __nv_bfloat16* Bb = (blk == 1 ? g_w16l : g_w16h) + ko;
        uint32_t sa = sb + SM_A(buf);
        uint32_t sbm = sb + SM_B(buf);
        #pragma unroll
        for (int p = 0; p < 4; ++p) {
            int r = p * 32 + lr;
            uint32_t so = SMEM_SWIZZLE_128B((uint32_t)(r * 128 + lc * 16));
            CPA16(sa + so,  Ab + (size_t)(m0 + r) * astr + lc * 8);
            CPA16(sbm + so, Bb + (size_t)(n0 + r) * KCAT + lc * 8);
        }
    };

    stage_load(0, 0);
    CPA_COMMIT();

    for (int s = 0; s < 30; ++s) {
        int buf = s & 1;
        if (s + 1 < 30) {
            stage_load(s + 1, buf ^ 1);
            CPA_COMMIT();
            CPA_WAIT(1);
        } else {
            CPA_WAIT(0);
        }
        __syncthreads();

        #pragma unroll
        for (int ks = 0; ks < 4; ++ks) {
            uint32_t afr[4][4];
            #pragma unroll
            for (int mt = 0; mt < 4; ++mt) {
                uint32_t ad = sb + SM_A(buf) + SMEM_SWIZZLE_128B(
                    (uint32_t)((a_row + mt * 16) * 128 + ks * 32 + a_kb));
                asm volatile("ldmatrix.sync.aligned.m8n8.x4.shared.b16 {%0,%1,%2,%3}, [%4];"
                             : "=r"(afr[mt][0]), "=r"(afr[mt][1]),
                               "=r"(afr[mt][2]), "=r"(afr[mt][3]) : "r"(ad));
            }
            uint32_t bfr[4][2];
            #pragma unroll
            for (int nt = 0; nt < 4; ++nt) {
                uint32_t bd = sb + SM_B(buf) + SMEM_SWIZZLE_128B(
                    (uint32_t)((b_row + nt * 8) * 128 + ks * 32 + b_kb));
                asm volatile("ldmatrix.sync.aligned.m8n8.x2.shared.b16 {%0,%1}, [%2];"
                             : "=r"(bfr[nt][0]), "=r"(bfr[nt][1]) : "r"(bd));
            }
            #pragma unroll
            for (int mt = 0; mt < 4; ++mt)
                #pragma unroll
                for (int nt = 0; nt < 4; ++nt) {
                    asm volatile(
                        "mma.sync.aligned.m16n8k16.row.col.f32.bf16.bf16.f32 "
                        "{%0,%1,%2,%3}, {%4,%5,%6,%7}, {%8,%9}, {%0,%1,%2,%3};"
                        : "+f"(acc[mt][nt][0]), "+f"(acc[mt][nt][1]),
                          "+f"(acc[mt][nt][2]), "+f"(acc[mt][nt][3])
                        : "r"(afr[mt][0]), "r"(afr[mt][1]),
                          "r"(afr[mt][2]), "r"(afr[mt][3]),
                          "r"(bfr[nt][0]), "r"(bfr[nt][1]));
                }
        }
        __syncthreads();
    }

    float* gsm = reinterpret_cast<float*>(smem + SM_G);
    {
        int gr = lane >> 2;
        int gc0 = 2 * (lane & 3);
        #pragma unroll
        for (int mt = 0; mt < 4; ++mt)
            #pragma unroll
            for (int nt = 0; nt < 4; ++nt) {
                int r0 = wm * 64 + mt * 16 + gr;
                int c  = wn * 32 + nt * 8 + gc0;
                gsm[r0 * GPITCH + c]       = acc[mt][nt][0];
                gsm[r0 * GPITCH + c + 1]   = acc[mt][nt][1];
                gsm[(r0 + 8) * GPITCH + c]     = acc[mt][nt][2];
                gsm[(r0 + 8) * GPITCH + c + 1] = acc[mt][nt][3];
            }
    }
    __syncthreads();

    {
        int r = tid >> 1, half = tid & 1;
        int m = m0 + r;
        if (t < g_lensS[m]) {
            const float* grow = gsm + r * GPITCH + half * 64;
            const float* brow = sbias + half * 64;
            size_t ci = (size_t)m * H + (n0 >> 2) + half * 16;
            #pragma unroll
            for (int u = 0; u < 16; ++u) {
                float iv = grow[4 * u + 0] + brow[4 * u + 0];
                float fv = grow[4 * u + 1] + brow[4 * u + 1];
                float gv = grow[4 * u + 2] + brow[4 * u + 2];
                float ov = grow[4 * u + 3] + brow[4 * u + 3];
                float cc = g_c[ci + u];
                cc = fsig(fv) * cc + fsig(iv) * ftanh(gv);
                g_c[ci + u] = cc;
                float hh = fsig(ov) * ftanh(cc);
                hnf[ci + u] = hh;
                __nv_bfloat16 hb16 = __float2bfloat16(hh);
                hnh[ci + u] = hb16;
                hnl[ci + u] = __float2bfloat16(hh - __bfloat162float(hb16));
            }
        }
    }
}

// ---------------- x-gate GEMM via mma.sync bf16 (split hi/lo) ----------------
// C[S,1024] = wc @ W^T + bias, fwd/bwd via blockIdx.z. K'' = 3072 (48 stages).
__global__ __launch_bounds__(256)
void k_xg_mma() {
    extern __shared__ char smem_raw[];
    const int m0 = blockIdx.y * 128;
    const int n0 = blockIdx.x * 128;
    const __nv_bfloat16* Bh = blockIdx.z ? g_wb16h : g_wf16h;
    const __nv_bfloat16* Bl = blockIdx.z ? g_wb16l : g_wf16l;
    const float* bias = blockIdx.z ? g_bxb : g_bxf;
    float* C = blockIdx.z ? g_xgb : g_xgf;

    char* smem = reinterpret_cast<char*>(
        (((uintptr_t)smem_raw) + 1023) & ~(uintptr_t)1023);
    uint32_t sb = (uint32_t)__cvta_generic_to_shared(smem);

    const int tid = threadIdx.x;
    const int wid = tid >> 5, lane = tid & 31;
    float* sbias = reinterpret_cast<float*>(smem + SM_BIAS);
    if (tid < 128) sbias[tid] = bias[n0 + tid];

    const int wm = wid >> 2;
    const int wn = wid & 3;

    float acc[4][4][4];
    #pragma unroll
    for (int i = 0; i < 4; i++)
        #pragma unroll
        for (int j = 0; j < 4; j++)
            #pragma unroll
            for (int k = 0; k < 4; k++) acc[i][j][k] = 0.f;

    const int lr = tid >> 3;
    const int lc = tid & 7;
    const int a_row = wm * 64 + ((lane >> 3) & 1) * 8 + (lane & 7);
    const int a_kb  = (lane >> 4) * 16;
    const int b_row = wn * 32 + (lane & 7);
    const int b_kb  = ((lane >> 3) & 1) * 16;

    auto stage_load = [&](int s, int buf) {
        int blk = s >> 4;                   // 16 stages per K-block of 1024
        int ko  = (s & 15) * 64;
        const __nv_bfloat16* Ab = (blk < 2 ? g_wch : g_wcl) + ko;
        const __nv_bfloat16* Bb = (blk == 1 ? Bl : Bh) + ko;
        uint32_t sa = sb + SM_A(buf);
        uint32_t sbm = sb + SM_B(buf);
        #pragma unroll
        for (int p = 0; p < 4; ++p) {
            int r = p * 32 + lr;
            uint32_t so = SMEM_SWIZZLE_128B((uint32_t)(r * 128 + lc * 16));
            CPA16(sa + so,  Ab + (size_t)(m0 + r) * G4HH + lc * 8);
            CPA16(sbm + so, Bb + (size_t)(n0 + r) * G4HH + lc * 8);
        }
    };

    stage_load(0, 0);
    CPA_COMMIT();

    for (int s = 0; s < 48; ++s) {
        int buf = s & 1;
        if (s + 1 < 48) {
            stage_load(s + 1, buf ^ 1);
            CPA_COMMIT();
            CPA_WAIT(1);
        } else {
            CPA_WAIT(0);
        }
        __syncthreads();

        #pragma unroll
        for (int ks = 0; ks < 4; ++ks) {
            uint32_t afr[4][4];
            #pragma unroll
            for (int mt = 0; mt < 4; ++mt) {
                uint32_t ad = sb + SM_A(buf) + SMEM_SWIZZLE_128B(
                    (uint32_t)((a_row + mt * 16) * 128 + ks * 32 + a_kb));
                asm volatile("ldmatrix.sync.aligned.m8n8.x4.shared.b16 {%0,%1,%2,%3}, [%4];"
                             : "=r"(afr[mt][0]), "=r"(afr[mt][1]),
                               "=r"(afr[mt][2]), "=r"(afr[mt][3]) : "r"(ad));
            }
            uint32_t bfr[4][2];
            #pragma unroll
            for (int nt = 0; nt < 4; ++nt) {
                uint32_t bd = sb + SM_B(buf) + SMEM_SWIZZLE_128B(
                    (uint32_t)((b_row + nt * 8) * 128 + ks * 32 + b_kb));
                asm volatile("ldmatrix.sync.aligned.m8n8.x2.shared.b16 {%0,%1}, [%2];"
                             : "=r"(bfr[nt][0]), "=r"(bfr[nt][1]) : "r"(bd));
            }
            #pragma unroll
            for (int mt = 0; mt < 4; ++mt)
                #pragma unroll
                for (int nt = 0; nt < 4; ++nt) {
                    asm volatile(
                        "mma.sync.aligned.m16n8k16.row.col.f32.bf16.bf16.f32 "
                        "{%0,%1,%2,%3}, {%4,%5,%6,%7}, {%8,%9}, {%0,%1,%2,%3};"
                        : "+f"(acc[mt][nt][0]), "+f"(acc[mt][nt][1]),
                          "+f"(acc[mt][nt][2]), "+f"(acc[mt][nt][3])
                        : "r"(afr[mt][0]), "r"(afr[mt][1]),
                          "r"(afr[mt][2]), "r"(afr[mt][3]),
                          "r"(bfr[nt][0]), "r"(bfr[nt][1]));
                }
        }
        __syncthreads();
    }

    // epilogue: bias + direct store
    {
        int gr = lane >> 2;
        int gc0 = 2 * (lane & 3);
        #pragma unroll
        for (int mt = 0; mt < 4; ++mt)
            #pragma unroll
            for (int nt = 0; nt < 4; ++nt) {
                int r = wm * 64 + mt * 16 + gr;
                int c = wn * 32 + nt * 8 + gc0;
                size_t base = (size_t)(m0 + r) * G4HH + n0 + c;
                float2 v0 = make_float2(acc[mt][nt][0] + sbias[c],
                                        acc[mt][nt][1] + sbias[c + 1]);
                float2 v1 = make_float2(acc[mt][nt][2] + sbias[c],
                                        acc[mt][nt][3] + sbias[c + 1]);
                *reinterpret_cast<float2*>(C + base) = v0;
                *reinterpret_cast<float2*>(C + base + (size_t)8 * G4HH) = v1;
            }
    }
}

// ---------------- word bi-LSTM recurrence: 2 clusters of 8 CTAs, 512 thr ----------
__global__ void __cluster_dims__(8, 1, 1) __launch_bounds__(512, 1)
k_word_lstm(const float* __restrict__ Whh_f, const float* __restrict__ Whh_b) {
    __shared__ __align__(16) float hb[2][HH];
    __shared__ float partial[512];

    unsigned rank;
    asm("mov.u32 %0, %%cluster_ctarank;" : "=r"(rank));
    int dir = blockIdx.x / 8;
    const float* Whh = dir ? Whh_b : Whh_f;
    const float* xg  = dir ? g_xgb : g_xgf;

    int tid = threadIdx.x;
    int p   = tid & 127;
    int q   = tid >> 7;
    int gte = p >> 5;
    int jj  = p & 31;
    int grow = gte * HH + (int)rank * 32 + jj;

    ull w2[32];
    const float4* wsrc = reinterpret_cast<const float4*>(Whh + (size_t)grow * HH + q * 64);
    #pragma unroll
    for (int i = 0; i < 16; i++) {
        float4 f = wsrc[i];
        w2[2 * i]     = pack2(f.x, f.y);
        w2[2 * i + 1] = pack2(f.z, f.w);
    }

    int lane = tid & 31;
    unsigned raA[8], raB[8];
    {
        unsigned loff0 = (unsigned)__cvta_generic_to_shared(&hb[0][rank * 32 + lane]);
        unsigned loff1 = (unsigned)__cvta_generic_to_shared(&hb[1][rank * 32 + lane]);
        #pragma unroll
        for (int peer = 0; peer < 8; ++peer) {
            asm("mapa.shared::cluster.u32 %0, %1, %2;" : "=r"(raA[peer]) : "r"(loff0), "r"(peer));
            asm("mapa.shared::cluster.u32 %0, %1, %2;" : "=r"(raB[peer]) : "r"(loff1), "r"(peer));
        }
    }

    if (tid < HH) hb[0][tid] = 0.f;
    __syncthreads();
    asm volatile("barrier.cluster.arrive.aligned;" ::: "memory");
    asm volatile("barrier.cluster.wait.aligned;"   ::: "memory");

    float c_reg = 0.f;
    int par = 0;
    const int xbase = (int)rank * 32 + lane;
    float xv0 = 0.f, xv1 = 0.f, xv2 = 0.f, xv3 = 0.f;
    if (tid < 32) {
        size_t r0 = (size_t)(dir ? (S - 1) : 0) * G4HH + xbase;
        xv0 = __ldg(&xg[r0]);       xv1 = __ldg(&xg[r0 + 256]);
        xv2 = __ldg(&xg[r0 + 512]); xv3 = __ldg(&xg[r0 + 768]);
    }

    for (int t = 0; t < S; ++t) {
        int row = dir ? (S - 1 - t) : t;

        const ull* hv = reinterpret_cast<const ull*>(&hb[par][q * 64]);
        ull a0 = 0ULL, a1 = 0ULL, a2 = 0ULL, a3 = 0ULL;
        #pragma unroll
        for (int i = 0; i < 32; i += 4) {
            a0 = ffma2(w2[i + 0], hv[i + 0], a0);
            a1 = ffma2(w2[i + 1], hv[i + 1], a1);
            a2 = ffma2(w2[i + 2], hv[i + 2], a2);
            a3 = ffma2(w2[i + 3], hv[i + 3], a3);
        }
        float l0, h0f, l1, h1f, l2, h2f, l3, h3f;
        unpack2(a0, l0, h0f); unpack2(a1, l1, h1f);
        unpack2(a2, l2, h2f); unpack2(a3, l3, h3f);
        partial[tid] = ((l0 + h0f) + (l1 + h1f)) + ((l2 + h2f) + (l3 + h3f));

        float nx0 = 0.f, nx1 = 0.f, nx2 = 0.f, nx3 = 0.f;
        if (tid < 32 && t + 1 < S) {
            int rn = dir ? (S - 2 - t) : (t + 1);
            size_t rb = (size_t)rn * G4HH + xbase;
            nx0 = __ldg(&xg[rb]);       nx1 = __ldg(&xg[rb + 256]);
            nx2 = __ldg(&xg[rb + 512]); nx3 = __ldg(&xg[rb + 768]);
        }
        __syncthreads();
        if (tid < 32) {
            float p0 = (partial[lane]       + partial[lane + 128])
                     + (partial[lane + 256] + partial[lane + 384]);
            float p1 = (partial[32 + lane]       + partial[32 + lane + 128])
                     + (partial[32 + lane + 256] + partial[32 + lane + 384]);
            float p2 = (partial[64 + lane]       + partial[64 + lane + 128])
                     + (partial[64 + lane + 256] + partial[64 + lane + 384]);
            float p3 = (partial[96 + lane]       + partial[96 + lane + 128])
                     + (partial[96 + lane + 256] + partial[96 + lane + 384]);
            float iv = fsig(p0 + xv0);
            float fv = fsig(p1 + xv1);
            float gg = ftanh(p2 + xv2);
            float ov = fsig(p3 + xv3);
            c_reg = fv * c_reg + iv * gg;
            float hnew = ov * ftanh(c_reg);
            g_out[(size_t)row * H + dir * HH + rank * 32 + lane] = hnew;
            if (par == 0) {
                #pragma unroll
                for (int peer = 0; peer < 8; ++peer)
                    asm volatile("st.shared::cluster.f32 [%0], %1;"
                                 :: "r"(raB[peer]), "f"(hnew) : "memory");
            } else {
                #pragma unroll
                for (int peer = 0; peer < 8; ++peer)
                    asm volatile("st.shared::cluster.f32 [%0], %1;"
                                 :: "r"(raA[peer]), "f"(hnew) : "memory");
            }
        }
        asm volatile("barrier.cluster.arrive.aligned;" ::: "memory");
        asm volatile("barrier.cluster.wait.aligned;"   ::: "memory");
        par ^= 1;
        xv0 = nx0; xv1 = nx1; xv2 = nx2; xv3 = nx3;
    }
}

// ---------------- output heads: logits + log_softmax ----------------
__global__ void k_logits(const float* __restrict__ W,   // [C,512]
                         const float* __restrict__ bias,
                         float* __restrict__ dst, int C) {
    __shared__ float row[H];
    __shared__ float red[64];
    int s = blockIdx.x, tid = threadIdx.x;
    for (int k = tid; k < H; k += blockDim.x) row[k] = g_out[(size_t)s * H + k];
    __syncthreads();
    float acc = bias[tid];
    const float4* w4 = reinterpret_cast<const float4*>(W + (size_t)tid * H);
    const float4* r4 = reinterpret_cast<const float4*>(row);
    #pragma unroll 8
    for (int q = 0; q < H / 4; q++) {
        float4 w = w4[q], r = r4[q];
        acc += w.x * r.x + w.y * r.y + w.z * r.z + w.w * r.w;
    }
    red[tid] = acc;
    __syncthreads();
    for (int off = C >> 1; off; off >>= 1) {
        if (tid < off) red[tid] = fmaxf(red[tid], red[tid + off]);
        __syncthreads();
    }
    float mx = red[0];
    __syncthreads();
    red[tid] = expf(acc - mx);
    __syncthreads();
    for (int off = C >> 1; off; off >>= 1) {
        if (tid < off) red[tid] += red[tid + off];
        __syncthreads();
    }
    float lse = mx + logf(red[0]);
    dst[(size_t)s * C + tid] = acc - lse;
}

// ---------------- launch ----------------
extern "C" void kernel_launch(void* const* d_in, const int* in_sizes, int n_in,
                              void* d_out, int out_size) {
    const int*   word_seq   = (const int*)  d_in[0];
    const int*   chars      = (const int*)  d_in[1];
    const int*   char_lens  = (const int*)  d_in[2];
    const int*   feat_seq   = (const int*)  d_in[3];
    const float* char_emb   = (const float*)d_in[4];
    const float* word_emb   = (const float*)d_in[5];
    const float* prefix_emb = (const float*)d_in[6];
    const float* Wih_c = (const float*)d_in[7];
    const float* Whh_c = (const float*)d_in[8];
    const float* bih_c = (const float*)d_in[9];
    const float* bhh_c = (const float*)d_in[10];
    const float* Wih_f = (const float*)d_in[11];
    const float* Whh_f = (const float*)d_in[12];
    const float* bih_f = (const float*)d_in[13];
    const float* bhh_f = (const float*)d_in[14];
    const float* Wih_b = (const float*)d_in[15];
    const float* Whh_b = (const float*)d_in[16];
    const float* bih_b = (const float*)d_in[17];
    const float* bhh_b = (const float*)d_in[18];
    const float* Wpos  = (const float*)d_in[19];
    const float* bpos  = (const float*)d_in[20];
    const float* Wner  = (const float*)d_in[21];
    const float* bner  = (const float*)d_in[22];
    float* out = (float*)d_out;

    float *p_hA, *p_hB;
    __nv_bfloat16 *p_xc16h, *p_xc16l, *p_h16hA, *p_h16lA, *p_h16hB, *p_h16lB;
    cudaGetSymbolAddress((void**)&p_hA,  g_hA);
    cudaGetSymbolAddress((void**)&p_hB,  g_hB);
    cudaGetSymbolAddress((void**)&p_xc16h, g_xc16h);
    cudaGetSymbolAddress((void**)&p_xc16l, g_xc16l);
    cudaGetSymbolAddress((void**)&p_h16hA, g_h16hA);
    cudaGetSymbolAddress((void**)&p_h16lA, g_h16lA);
    cudaGetSymbolAddress((void**)&p_h16hB, g_h16hB);
    cudaGetSymbolAddress((void**)&p_h16lB, g_h16lB);

    cudaFuncSetAttribute(k_char_mma, cudaFuncAttributeMaxDynamicSharedMemorySize,
                         SMEM_MMA_BYTES);
    cudaFuncSetAttribute(k_xg_mma, cudaFuncAttributeMaxDynamicSharedMemorySize,
                         SMEM_MMA_BYTES);

    // prep: sort, char prep, xg prep, gather
    k_sort<<<1, 256>>>(char_lens);
    k_prep_all<<<5120 + 8 + 8192, 256>>>(Wih_c, Whh_c, bih_c, bhh_c,
                                         feat_seq, prefix_emb);
    k_prep_xg<<<8200, 256>>>(Wih_f, Wih_b, bih_f, bhh_f, bih_b, bhh_b);
    k_gather_xc<<<(L * S * 64) / 256, 256>>>(chars, char_emb);

    // char LSTM: 16 mma.sync steps (cp.async pipelined), h ping-pong, early-exit
    dim3 gridC(G4H / 128, S / 128);
    for (int t = 0; t < L; ++t) {
        __nv_bfloat16* hch = (t & 1) ? p_h16hB : p_h16hA;
        __nv_bfloat16* hcl = (t & 1) ? p_h16lB : p_h16lA;
        __nv_bfloat16* hnh = (t & 1) ? p_h16hA : p_h16hB;
        __nv_bfloat16* hnl = (t & 1) ? p_h16lA : p_h16lB;
        float*         hnf = (t & 1) ? p_hA    : p_hB;
        k_char_mma<<<gridC, 256, SMEM_MMA_BYTES>>>(
            p_xc16h + (size_t)t * S * EC, p_xc16l + (size_t)t * S * EC,
            hch, hcl, hnh, hnl, hnf, t);
    }

    // word LSTM input (bf16 hi/lo) + x-gate GEMM via HMMA (fwd+bwd)
    k_build_wc16<<<(S * 512) / 256, 256>>>(word_seq, word_emb);
    dim3 gridX(G4HH / 128, S / 128, 2);
    k_xg_mma<<<gridX, 256, SMEM_MMA_BYTES>>>();

    // sequential bi-LSTM recurrence (2 clusters of 8 CTAs, fwd + bwd concurrent)
    k_word_lstm<<<16, 512>>>(Whh_f, Whh_b);

    // output heads
    k_logits<<<S, NPOS>>>(Wpos, bpos, out, NPOS);
    k_logits<<<S, NNER>>>(Wner, bner, out + (size_t)S * NPOS, NNER);

    (void)in_sizes; (void)n_in; (void)out_size;
}

// round 16
// speedup vs baseline: 1.4306x; 1.0438x over previous
#include <cuda_runtime.h>
#include <cuda_bf16.h>
#include <cstdint>
#include <cstddef>
#include <math.h>

#define S    4096
#define L    16
#define H    512
#define EC   128
#define EW   512
#define HH   256
#define G4H  2048   // 4*H
#define G4HH 1024   // 4*HH
#define NPOS 64
#define NNER 32
#define KCAT 640    // EC + H

typedef unsigned long long ull;

// ---------------- scratch (device globals; no dynamic allocation) ----------------
__device__ __nv_bfloat16 g_xc16h[(size_t)L * S * EC];  // char embeddings bf16-hi
__device__ __nv_bfloat16 g_xc16l[(size_t)L * S * EC];  // bf16-lo
__device__ __nv_bfloat16 g_h16hA[(size_t)S * H];       // h bf16-hi ping
__device__ __nv_bfloat16 g_h16lA[(size_t)S * H];       // h bf16-lo ping
__device__ __nv_bfloat16 g_h16hB[(size_t)S * H];       // h bf16-hi pong
__device__ __nv_bfloat16 g_h16lB[(size_t)S * H];       // h bf16-lo pong
__device__ __nv_bfloat16 g_w16h[(size_t)G4H * KCAT];   // permuted Wcat bf16-hi
__device__ __nv_bfloat16 g_w16l[(size_t)G4H * KCAT];   // permuted Wcat bf16-lo
__device__ __nv_bfloat16 g_wch[(size_t)S * G4HH];      // wc bf16-hi [S,1024]
__device__ __nv_bfloat16 g_wcl[(size_t)S * G4HH];      // wc bf16-lo
__device__ __nv_bfloat16 g_wf16h[(size_t)G4HH * G4HH]; // Wih_f bf16-hi [1024,1024]
__device__ __nv_bfloat16 g_wf16l[(size_t)G4HH * G4HH];
__device__ __nv_bfloat16 g_wb16h[(size_t)G4HH * G4HH]; // Wih_b bf16-hi
__device__ __nv_bfloat16 g_wb16l[(size_t)G4HH * G4HH];
__device__ float g_bxf[G4HH];                  // bih_f+bhh_f
__device__ float g_bxb[G4HH];                  // bih_b+bhh_b
__device__ float g_hA[(size_t)S * H];          // char LSTM hidden fp32 ping
__device__ float g_hB[(size_t)S * H];          // char LSTM hidden fp32 pong
__device__ float g_c [(size_t)S * H];          // char LSTM cell (sorted order)
__device__ float g_xgf[(size_t)S * G4HH];      // precomputed x-gates fwd
__device__ float g_xgb[(size_t)S * G4HH];      // precomputed x-gates bwd
__device__ float g_out[(size_t)S * H];         // bi-LSTM output [S,512]
__device__ float g_biasP[G4H];                 // permuted bih_c+bhh_c
__device__ int   g_perm[S];                    // sorted slot -> original index
__device__ int   g_inv[S];                     // original index -> sorted slot
__device__ int   g_lensS[S];                   // lens in sorted order (descending)
__device__ int   g_cnt[L];                     // cnt[t] = #words with len > t

// fast transcendentals (err ~1e-7 rel; tolerance is 1e-3)
__device__ __forceinline__ float fsig(float x) {
    return __fdividef(1.f, 1.f + __expf(-x));
}
__device__ __forceinline__ float ftanh(float x) {
    return 1.f - __fdividef(2.f, __expf(2.f * x) + 1.f);
}

__device__ __forceinline__ ull pack2(float x, float y) {
    ull r; asm("mov.b64 %0,{%1,%2};" : "=l"(r) : "f"(x), "f"(y)); return r;
}
__device__ __forceinline__ void unpack2(ull v, float& x, float& y) {
    asm("mov.b64 {%0,%1},%2;" : "=f"(x), "=f"(y) : "l"(v));
}
__device__ __forceinline__ ull ffma2(ull a, ull b, ull c) {
    ull d; asm("fma.rn.f32x2 %0,%1,%2,%3;" : "=l"(d) : "l"(a), "l"(b), "l"(c)); return d;
}

#define SMEM_SWIZZLE_128B(bo) ((bo) ^ (((bo) >> 3) & 0x70))

// ---------------- counting sort by char length (descending) ----------------
__global__ void k_sort(const int* __restrict__ lens) {
    __shared__ int hist[17], off[17];
    int tid = threadIdx.x;
    if (tid < 17) hist[tid] = 0;
    __syncthreads();
    for (int s = tid; s < S; s += blockDim.x) atomicAdd(&hist[lens[s]], 1);
    __syncthreads();
    if (tid == 0) {
        int acc = 0;
        for (int l = 16; l >= 1; --l) { off[l] = acc; acc += hist[l]; }
        for (int t = 0; t < L; ++t) g_cnt[t] = off[t + 1] + hist[t + 1];
    }
    __syncthreads();
    for (int s = tid; s < S; s += blockDim.x) {
        int l = lens[s];
        int pos = atomicAdd(&off[l], 1);
        g_perm[pos] = s;
        g_inv[s] = pos;
        g_lensS[pos] = l;
    }
}

// ---------------- fused prep: bf16 char weights + bias + h/c init ----------------
__global__ void k_prep_all(const float* __restrict__ Wih_c,
                           const float* __restrict__ Whh_c,
                           const float* __restrict__ bih_c,
                           const float* __restrict__ bhh_c,
                           const int*   __restrict__ feat_seq,
                           const float* __restrict__ prefix_emb) {
    int b = blockIdx.x;
    if (b < 5120) {
        int idx = b * 256 + threadIdx.x;               // < 2048*640
        int n = idx / KCAT, k = idx % KCAT;
        int jh = n >> 2, g = n & 3;
        int row = g * H + jh;
        float w = (k < EC) ? Wih_c[(size_t)row * EC + k]
                           : Whh_c[(size_t)row * H + (k - EC)];
        __nv_bfloat16 hi = __float2bfloat16(w);
        g_w16h[idx] = hi;
        g_w16l[idx] = __float2bfloat16(w - __bfloat162float(hi));
    } else if (b < 5128) {
        int n = (b - 5120) * 256 + threadIdx.x;        // < 2048
        int jh = n >> 2, g = n & 3;
        int row = g * H + jh;
        g_biasP[n] = bih_c[row] + bhh_c[row];
    } else {
        int idx = (b - 5128) * 256 + threadIdx.x;      // < S*512
        int j = idx & 511;
        int slot = idx >> 9;
        int s = g_perm[slot];
        float h0 = prefix_emb[(size_t)feat_seq[s] * H + j];
        g_hA[idx] = h0;
        __nv_bfloat16 hi = __float2bfloat16(h0);
        g_h16hA[idx] = hi;
        g_h16lA[idx] = __float2bfloat16(h0 - __bfloat162float(hi));
        g_c[idx] = 0.f;
    }
}

// ---------------- prep x-gate weights: Wih_f/b -> bf16 hi/lo, biases ------------
__global__ void k_prep_xg(const float* __restrict__ Wih_f,
                          const float* __restrict__ Wih_b,
                          const float* __restrict__ b1f, const float* __restrict__ b2f,
                          const float* __restrict__ b1b, const float* __restrict__ b2b) {
    int b = blockIdx.x;
    if (b < 4096) {
        int idx = b * 256 + threadIdx.x;               // < 1024*1024
        float w = Wih_f[idx];
        __nv_bfloat16 hi = __float2bfloat16(w);
        g_wf16h[idx] = hi;
        g_wf16l[idx] = __float2bfloat16(w - __bfloat162float(hi));
    } else if (b < 8192) {
        int idx = (b - 4096) * 256 + threadIdx.x;
        float w = Wih_b[idx];
        __nv_bfloat16 hi = __float2bfloat16(w);
        g_wb16h[idx] = hi;
        g_wb16l[idx] = __float2bfloat16(w - __bfloat162float(hi));
    } else if (b < 8196) {
        int n = (b - 8192) * 256 + threadIdx.x;        // < 1024
        g_bxf[n] = b1f[n] + b2f[n];
    } else {
        int n = (b - 8196) * 256 + threadIdx.x;
        g_bxb[n] = b1b[n] + b2b[n];
    }
}

// ---------------- embedding gather: char emb -> bf16 hi/lo (sorted order) -------
__global__ void k_gather_xc(const int* __restrict__ chars,
                            const float* __restrict__ char_emb) {
    int idx = blockIdx.x * blockDim.x + threadIdx.x;   // < L*S*64 (pairs)
    int e2 = idx & 63;
    int slot = (idx >> 6) & (S - 1);
    int t = idx >> 18;
    int s = g_perm[slot];
    float2 v = *reinterpret_cast<const float2*>(
        char_emb + (size_t)chars[s * L + t] * EC + e2 * 2);
    __nv_bfloat16 h0 = __float2bfloat16(v.x), h1 = __float2bfloat16(v.y);
    __nv_bfloat16 l0 = __float2bfloat16(v.x - __bfloat162float(h0));
    __nv_bfloat16 l1 = __float2bfloat16(v.y - __bfloat162float(h1));
    reinterpret_cast<__nv_bfloat162*>(g_xc16h)[idx] = __nv_bfloat162(h0, h1);
    reinterpret_cast<__nv_bfloat162*>(g_xc16l)[idx] = __nv_bfloat162(l0, l1);
}

// ---------------- word LSTM input -> bf16 hi/lo directly ----------------
__global__ void k_build_wc16(const int* __restrict__ word_seq,
                             const float* __restrict__ word_emb) {
    int idx = blockIdx.x * blockDim.x + threadIdx.x;   // < S*512 (pairs)
    int k2 = idx & 511;
    int s = idx >> 9;
    float2 v;
    if (k2 < 256) {
        v = reinterpret_cast<const float2*>(word_emb)[(size_t)word_seq[s] * 256 + k2];
    } else {
        int slot = g_inv[s];
        int len = g_lensS[slot];
        const float2* hp = reinterpret_cast<const float2*>((len & 1) ? g_hB : g_hA);
        v = hp[(size_t)slot * 256 + (k2 - 256)];
    }
    __nv_bfloat16 h0 = __float2bfloat16(v.x), h1 = __float2bfloat16(v.y);
    __nv_bfloat16 l0 = __float2bfloat16(v.x - __bfloat162float(h0));
    __nv_bfloat16 l1 = __float2bfloat16(v.y - __bfloat162float(h1));
    reinterpret_cast<__nv_bfloat162*>(g_wch)[idx] = __nv_bfloat162(h0, h1);
    reinterpret_cast<__nv_bfloat162*>(g_wcl)[idx] = __nv_bfloat162(l0, l1);
}

// ---------------- HMMA machinery (char: 128x64 tile; xg: 128x128 tile) ----------
#define CPA16(dst, src) \
    asm volatile("cp.async.cg.shared.global [%0], [%1], 16;" \
                 :: "r"(dst), "l"(src) : "memory")
#define CPA_COMMIT() asm volatile("cp.async.commit_group;" ::: "memory")
#define CPA_WAIT(n)  asm volatile("cp.async.wait_group %0;" :: "n"(n) : "memory")

// --- char kernel smem layout: 128x64 tile, 2 CTAs/SM target ---
#define CSM_BIAS 0
#define CSM_A(b) (1024 + (b) * 16384)      // A: 128 rows x 128B = 16KB
#define CSM_B(b) (33792 + (b) * 8192)      // B:  64 rows x 128B =  8KB
#define CSM_G    1024                       // gates 128 x 68 floats (reuse)
#define CGPITCH  68
#define CSMEM_BYTES (1024 + 128 * CGPITCH * 4 + 1024)   // ~36.8KB < 50KB loads region
// total allocated = max(regions): loads end at 33792+16384=50176; use that
#define CSMEM_ALLOC 51200

__global__ __launch_bounds__(256)
void k_char_mma(const __nv_bfloat16* __restrict__ xh,
                const __nv_bfloat16* __restrict__ xl,
                const __nv_bfloat16* __restrict__ hch,
                const __nv_bfloat16* __restrict__ hcl,
                __nv_bfloat16* __restrict__ hnh,
                __nv_bfloat16* __restrict__ hnl,
                float* __restrict__ hnf,
                int t) {
    extern __shared__ char smem_raw[];
    const int cnt = g_cnt[t];
    const int m0 = blockIdx.y * 128;
    if (m0 >= cnt) return;
    const int n0 = blockIdx.x * 64;

    char* smem = reinterpret_cast<char*>(
        (((uintptr_t)smem_raw) + 1023) & ~(uintptr_t)1023);
    uint32_t sb = (uint32_t)__cvta_generic_to_shared(smem);

    const int tid = threadIdx.x;
    const int wid = tid >> 5, lane = tid & 31;
    float* sbias = reinterpret_cast<float*>(smem + CSM_BIAS);
    if (tid < 64) sbias[tid] = g_biasP[n0 + tid];

    const int wm = wid >> 1;       // 0..3 (m block of 32)
    const int wn = wid & 1;        // 0..1 (n block of 32)

    float acc[2][4][4];
    #pragma unroll
    for (int i = 0; i < 2; i++)
        #pragma unroll
        for (int j = 0; j < 4; j++)
            #pragma unroll
            for (int k = 0; k < 4; k++) acc[i][j][k] = 0.f;

    const int lr = tid >> 3;            // 0..31
    const int lc = tid & 7;
    const int a_row = wm * 32 + ((lane >> 3) & 1) * 8 + (lane & 7);   // + mt*16
    const int a_kb  = (lane >> 4) * 16;
    const int b_row = wn * 32 + (lane & 7);                           // + nt*8
    const int b_kb  = ((lane >> 3) & 1) * 16;

    auto stage_load = [&](int s, int buf) {
        int kk0 = s * 64;
        int blk = kk0 / 640;
        int ko  = kk0 - blk * 640;
        const __nv_bfloat16* Ab;
        size_t astr;
        if (ko < EC) { Ab = (blk < 2 ? xh : xl) + ko; astr = EC; }
        else         { Ab = (blk < 2 ? hch : hcl) + (ko - EC); astr = H; }
        const __nv_bfloat16* Bb = (blk == 1 ? g_w16l : g_w16h) + ko;
        uint32_t sa = sb + CSM_A(buf);
        uint32_t sbm = sb + CSM_B(buf);
        #pragma unroll
        for (int p = 0; p < 4; ++p) {
            int r = p * 32 + lr;
            uint32_t so = SMEM_SWIZZLE_128B((uint32_t)(r * 128 + lc * 16));
            CPA16(sa + so, Ab + (size_t)(m0 + r) * astr + lc * 8);
        }
        #pragma unroll
        for (int p = 0; p < 2; ++p) {
            int r = p * 32 + lr;
            uint32_t so = SMEM_SWIZZLE_128B((uint32_t)(r * 128 + lc * 16));
            CPA16(sbm + so, Bb + (size_t)(n0 + r) * KCAT + lc * 8);
        }
    };

    stage_load(0, 0);
    CPA_COMMIT();

    for (int s = 0; s < 30; ++s) {
        int buf = s & 1;
        if (s + 1 < 30) {
            stage_load(s + 1, buf ^ 1);
            CPA_COMMIT();
            CPA_WAIT(1);
        } else {
            CPA_WAIT(0);
        }
        __syncthreads();

        #pragma unroll
        for (int ks = 0; ks < 4; ++ks) {
            uint32_t afr[2][4];
            #pragma unroll
            for (int mt = 0; mt < 2; ++mt) {
                uint32_t ad = sb + CSM_A(buf) + SMEM_SWIZZLE_128B(
                    (uint32_t)((a_row + mt * 16) * 128 + ks * 32 + a_kb));
                asm volatile("ldmatrix.sync.aligned.m8n8.x4.shared.b16 {%0,%1,%2,%3}, [%4];"
                             : "=r"(afr[mt][0]), "=r"(afr[mt][1]),
                               "=r"(afr[mt][2]), "=r"(afr[mt][3]) : "r"(ad));
            }
            uint32_t bfr[4][2];
            #pragma unroll
            for (int nt = 0; nt < 4; ++nt) {
                uint32_t bd = sb + CSM_B(buf) + SMEM_SWIZZLE_128B(
                    (uint32_t)((b_row + nt * 8) * 128 + ks * 32 + b_kb));
                asm volatile("ldmatrix.sync.aligned.m8n8.x2.shared.b16 {%0,%1}, [%2];"
                             : "=r"(bfr[nt][0]), "=r"(bfr[nt][1]) : "r"(bd));
            }
            #pragma unroll
            for (int mt = 0; mt < 2; ++mt)
                #pragma unroll
                for (int nt = 0; nt < 4; ++nt) {
                    asm volatile(
                        "mma.sync.aligned.m16n8k16.row.col.f32.bf16.bf16.f32 "
                        "{%0,%1,%2,%3}, {%4,%5,%6,%7}, {%8,%9}, {%0,%1,%2,%3};"
                        : "+f"(acc[mt][nt][0]), "+f"(acc[mt][nt][1]),
                          "+f"(acc[mt][nt][2]), "+f"(acc[mt][nt][3])
                        : "r"(afr[mt][0]), "r"(afr[mt][1]),
                          "r"(afr[mt][2]), "r"(afr[mt][3]),
                          "r"(bfr[nt][0]), "r"(bfr[nt][1]));
                }
        }
        __syncthreads();
    }

    float* gsm = reinterpret_cast<float*>(smem + CSM_G);
    {
        int gr = lane >> 2;
        int gc0 = 2 * (lane & 3);
        #pragma unroll
        for (int mt = 0; mt < 2; ++mt)
            #pragma unroll
            for (int nt = 0; nt < 4; ++nt) {
                int r0 = wm * 32 + mt * 16 + gr;
                int c  = wn * 32 + nt * 8 + gc0;
                gsm[r0 * CGPITCH + c]       = acc[mt][nt][0];
                gsm[r0 * CGPITCH + c + 1]   = acc[mt][nt][1];
                gsm[(r0 + 8) * CGPITCH + c]     = acc[mt][nt][2];
                gsm[(r0 + 8) * CGPITCH + c + 1] = acc[mt][nt][3];
            }
    }
    __syncthreads();

    // fused LSTM cell: 2 threads per row, 8 units each (64 gate cols per row)
    {
        int r = tid >> 1, half = tid & 1;
        int m = m0 + r;
        if (t < g_lensS[m]) {
            const float* grow = gsm + r * CGPITCH + half * 32;
            const float* brow = sbias + half * 32;
            size_t ci = (size_t)m * H + (n0 >> 2) + half * 8;
            #pragma unroll
            for (int u = 0; u < 8; ++u) {
                float iv = grow[4 * u + 0] + brow[4 * u + 0];
                float fv = grow[4 * u + 1] + brow[4 * u + 1];
                float gv = grow[4 * u + 2] + brow[4 * u + 2];
                float ov = grow[4 * u + 3] + brow[4 * u + 3];
                float cc = g_c[ci + u];
                cc = fsig(fv) * cc + fsig(iv) * ftanh(gv);
                g_c[ci + u] = cc;
                float hh = fsig(ov) * ftanh(cc);
                hnf[ci + u] = hh;
                __nv_bfloat16 hb16 = __float2bfloat16(hh);
                hnh[ci + u] = hb16;
                hnl[ci + u] = __float2bfloat16(hh - __bfloat162float(hb16));
            }
        }
    }
}

// ---------------- x-gate GEMM via mma.sync bf16 (128x128 tile, unchanged) -------
#define SM_BIAS 0
#define SM_A(b) (1024 + (b) * 16384)
#define SM_B(b) (33792 + (b) * 16384)
#define SMEM_XG_BYTES (33792 + 2 * 16384 + 1024)

__global__ __launch_bounds__(256)
void k_xg_mma() {
    extern __shared__ char smem_raw[];
    const int m0 = blockIdx.y * 128;
    const int n0 = blockIdx.x * 128;
    const __nv_bfloat16* Bh = blockIdx.z ? g_wb16h : g_wf16h;
    const __nv_bfloat16* Bl = blockIdx.z ? g_wb16l : g_wf16l;
    const float* bias = blockIdx.z ? g_bxb : g_bxf;
    float* C = blockIdx.z ? g_xgb : g_xgf;

    char* smem = reinterpret_cast<char*>(
        (((uintptr_t)smem_raw) + 1023) & ~(uintptr_t)1023);
    uint32_t sb = (uint32_t)__cvta_generic_to_shared(smem);

    const int tid = threadIdx.x;
    const int wid = tid >> 5, lane = tid & 31;
    float* sbias = reinterpret_cast<float*>(smem + SM_BIAS);
    if (tid < 128) sbias[tid] = bias[n0 + tid];

    const int wm = wid >> 2;
    const int wn = wid & 3;

    float acc[4][4][4];
    #pragma unroll
    for (int i = 0; i < 4; i++)
        #pragma unroll
        for (int j = 0; j < 4; j++)
            #pragma unroll
            for (int k = 0; k < 4; k++) acc[i][j][k] = 0.f;

    const int lr = tid >> 3;
    const int lc = tid & 7;
    const int a_row = wm * 64 + ((lane >> 3) & 1) * 8 + (lane & 7);
    const int a_kb  = (lane >> 4) * 16;
    const int b_row = wn * 32 + (lane & 7);
    const int b_kb  = ((lane >> 3) & 1) * 16;

    auto stage_load = [&](int s, int buf) {
        int blk = s >> 4;
        int ko  = (s & 15) * 64;
        const __nv_bfloat16* Ab = (blk < 2 ? g_wch : g_wcl) + ko;
        const __nv_bfloat16* Bb = (blk == 1 ? Bl : Bh) + ko;
        uint32_t sa = sb + SM_A(buf);
        uint32_t sbm = sb + SM_B(buf);
        #pragma unroll
        for (int p = 0; p < 4; ++p) {
            int r = p * 32 + lr;
            uint32_t so = SMEM_SWIZZLE_128B((uint32_t)(r * 128 + lc * 16));
            CPA16(sa + so,  Ab + (size_t)(m0 + r) * G4HH + lc * 8);
            CPA16(sbm + so, Bb + (size_t)(n0 + r) * G4HH + lc * 8);
        }
    };

    stage_load(0, 0);
    CPA_COMMIT();

    for (int s = 0; s < 48; ++s) {
        int buf = s & 1;
        if (s + 1 < 48) {
            stage_load(s + 1, buf ^ 1);
            CPA_COMMIT();
            CPA_WAIT(1);
        } else {
            CPA_WAIT(0);
        }
        __syncthreads();

        #pragma unroll
        for (int ks = 0; ks < 4; ++ks) {
            uint32_t afr[4][4];
            #pragma unroll
            for (int mt = 0; mt < 4; ++mt) {
                uint32_t ad = sb + SM_A(buf) + SMEM_SWIZZLE_128B(
                    (uint32_t)((a_row + mt * 16) * 128 + ks * 32 + a_kb));
                asm volatile("ldmatrix.sync.aligned.m8n8.x4.shared.b16 {%0,%1,%2,%3}, [%4];"
                             : "=r"(afr[mt][0]), "=r"(afr[mt][1]),
                               "=r"(afr[mt][2]), "=r"(afr[mt][3]) : "r"(ad));
            }
            uint32_t bfr[4][2];
            #pragma unroll
            for (int nt = 0; nt < 4; ++nt) {
                uint32_t bd = sb + SM_B(buf) + SMEM_SWIZZLE_128B(
                    (uint32_t)((b_row + nt * 8) * 128 + ks * 32 + b_kb));
                asm volatile("ldmatrix.sync.aligned.m8n8.x2.shared.b16 {%0,%1}, [%2];"
                             : "=r"(bfr[nt][0]), "=r"(bfr[nt][1]) : "r"(bd));
            }
            #pragma unroll
            for (int mt = 0; mt < 4; ++mt)
                #pragma unroll
                for (int nt = 0; nt < 4; ++nt) {
                    asm volatile(
                        "mma.sync.aligned.m16n8k16.row.col.f32.bf16.bf16.f32 "
                        "{%0,%1,%2,%3}, {%4,%5,%6,%7}, {%8,%9}, {%0,%1,%2,%3};"
                        : "+f"(acc[mt][nt][0]), "+f"(acc[mt][nt][1]),
                          "+f"(acc[mt][nt][2]), "+f"(acc[mt][nt][3])
                        : "r"(afr[mt][0]), "r"(afr[mt][1]),
                          "r"(afr[mt][2]), "r"(afr[mt][3]),
                          "r"(bfr[nt][0]), "r"(bfr[nt][1]));
                }
        }
        __syncthreads();
    }

    {
        int gr = lane >> 2;
        int gc0 = 2 * (lane & 3);
        #pragma unroll
        for (int mt = 0; mt < 4; ++mt)
            #pragma unroll
            for (int nt = 0; nt < 4; ++nt) {
                int r = wm * 64 + mt * 16 + gr;
                int c = wn * 32 + nt * 8 + gc0;
                size_t base = (size_t)(m0 + r) * G4HH + n0 + c;
                float2 v0 = make_float2(acc[mt][nt][0] + sbias[c],
                                        acc[mt][nt][1] + sbias[c + 1]);
                float2 v1 = make_float2(acc[mt][nt][2] + sbias[c],
                                        acc[mt][nt][3] + sbias[c + 1]);
                *reinterpret_cast<float2*>(C + base) = v0;
                *reinterpret_cast<float2*>(C + base + (size_t)8 * G4HH) = v1;
            }
    }
}

// ---------------- word bi-LSTM recurrence: 2 clusters of 8 CTAs, 512 thr ----------
__global__ void __cluster_dims__(8, 1, 1) __launch_bounds__(512, 1)
k_word_lstm(const float* __restrict__ Whh_f, const float* __restrict__ Whh_b) {
    __shared__ __align__(16) float hb[2][HH];
    __shared__ float partial[512];

    unsigned rank;
    asm("mov.u32 %0, %%cluster_ctarank;" : "=r"(rank));
    int dir = blockIdx.x / 8;
    const float* Whh = dir ? Whh_b : Whh_f;
    const float* xg  = dir ? g_xgb : g_xgf;

    int tid = threadIdx.x;
    int p   = tid & 127;
    int q   = tid >> 7;
    int gte = p >> 5;
    int jj  = p & 31;
    int grow = gte * HH + (int)rank * 32 + jj;

    ull w2[32];
    const float4* wsrc = reinterpret_cast<const float4*>(Whh + (size_t)grow * HH + q * 64);
    #pragma unroll
    for (int i = 0; i < 16; i++) {
        float4 f = wsrc[i];
        w2[2 * i]     = pack2(f.x, f.y);
        w2[2 * i + 1] = pack2(f.z, f.w);
    }

    int lane = tid & 31;
    unsigned raA[8], raB[8];
    {
        unsigned loff0 = (unsigned)__cvta_generic_to_shared(&hb[0][rank * 32 + lane]);
        unsigned loff1 = (unsigned)__cvta_generic_to_shared(&hb[1][rank * 32 + lane]);
        #pragma unroll
        for (int peer = 0; peer < 8; ++peer) {
            asm("mapa.shared::cluster.u32 %0, %1, %2;" : "=r"(raA[peer]) : "r"(loff0), "r"(peer));
            asm("mapa.shared::cluster.u32 %0, %1, %2;" : "=r"(raB[peer]) : "r"(loff1), "r"(peer));
        }
    }

    if (tid < HH) hb[0][tid] = 0.f;
    __syncthreads();
    asm volatile("barrier.cluster.arrive.aligned;" ::: "memory");
    asm volatile("barrier.cluster.wait.aligned;"   ::: "memory");

    float c_reg = 0.f;
    int par = 0;
    const int xbase = (int)rank * 32 + lane;
    float xv0 = 0.f, xv1 = 0.f, xv2 = 0.f, xv3 = 0.f;
    if (tid < 32) {
        size_t r0 = (size_t)(dir ? (S - 1) : 0) * G4HH + xbase;
        xv0 = __ldg(&xg[r0]);       xv1 = __ldg(&xg[r0 + 256]);
        xv2 = __ldg(&xg[r0 + 512]); xv3 = __ldg(&xg[r0 + 768]);
    }

    for (int t = 0; t < S; ++t) {
        int row = dir ? (S - 1 - t) : t;

        const ull* hv = reinterpret_cast<const ull*>(&hb[par][q * 64]);
        ull a0 = 0ULL, a1 = 0ULL, a2 = 0ULL, a3 = 0ULL;
        #pragma unroll
        for (int i = 0; i < 32; i += 4) {
            a0 = ffma2(w2[i + 0], hv[i + 0], a0);
            a1 = ffma2(w2[i + 1], hv[i + 1], a1);
            a2 = ffma2(w2[i + 2], hv[i + 2], a2);
            a3 = ffma2(w2[i + 3], hv[i + 3], a3);
        }
        float l0, h0f, l1, h1f, l2, h2f, l3, h3f;
        unpack2(a0, l0, h0f); unpack2(a1, l1, h1f);
        unpack2(a2, l2, h2f); unpack2(a3, l3, h3f);
        partial[tid] = ((l0 + h0f) + (l1 + h1f)) + ((l2 + h2f) + (l3 + h3f));

        float nx0 = 0.f, nx1 = 0.f, nx2 = 0.f, nx3 = 0.f;
        if (tid < 32 && t + 1 < S) {
            int rn = dir ? (S - 2 - t) : (t + 1);
            size_t rb = (size_t)rn * G4HH + xbase;
            nx0 = __ldg(&xg[rb]);       nx1 = __ldg(&xg[rb + 256]);
            nx2 = __ldg(&xg[rb + 512]); nx3 = __ldg(&xg[rb + 768]);
        }
        __syncthreads();
        if (tid < 32) {
            float p0 = (partial[lane]       + partial[lane + 128])
                     + (partial[lane + 256] + partial[lane + 384]);
            float p1 = (partial[32 + lane]       + partial[32 + lane + 128])
                     + (partial[32 + lane + 256] + partial[32 + lane + 384]);
            float p2 = (partial[64 + lane]       + partial[64 + lane + 128])
                     + (partial[64 + lane + 256] + partial[64 + lane + 384]);
            float p3 = (partial[96 + lane]       + partial[96 + lane + 128])
                     + (partial[96 + lane + 256] + partial[96 + lane + 384]);
            float iv = fsig(p0 + xv0);
            float fv = fsig(p1 + xv1);
            float gg = ftanh(p2 + xv2);
            float ov = fsig(p3 + xv3);
            c_reg = fv * c_reg + iv * gg;
            float hnew = ov * ftanh(c_reg);
            g_out[(size_t)row * H + dir * HH + rank * 32 + lane] = hnew;
            if (par == 0) {
                #pragma unroll
                for (int peer = 0; peer < 8; ++peer)
                    asm volatile("st.shared::cluster.f32 [%0], %1;"
                                 :: "r"(raB[peer]), "f"(hnew) : "memory");
            } else {
                #pragma unroll
                for (int peer = 0; peer < 8; ++peer)
                    asm volatile("st.shared::cluster.f32 [%0], %1;"
                                 :: "r"(raA[peer]), "f"(hnew) : "memory");
            }
        }
        asm volatile("barrier.cluster.arrive.aligned;" ::: "memory");
        asm volatile("barrier.cluster.wait.aligned;"   ::: "memory");
        par ^= 1;
        xv0 = nx0; xv1 = nx1; xv2 = nx2; xv3 = nx3;
    }
}

// ---------------- output heads: logits + log_softmax ----------------
__global__ void k_logits(const float* __restrict__ W,   // [C,512]
                         const float* __restrict__ bias,
                         float* __restrict__ dst, int C) {
    __shared__ float row[H];
    __shared__ float red[64];
    int s = blockIdx.x, tid = threadIdx.x;
    for (int k = tid; k < H; k += blockDim.x) row[k] = g_out[(size_t)s * H + k];
    __syncthreads();
    float acc = bias[tid];
    const float4* w4 = reinterpret_cast<const float4*>(W + (size_t)tid * H);
    const float4* r4 = reinterpret_cast<const float4*>(row);
    #pragma unroll 8
    for (int q = 0; q < H / 4; q++) {
        float4 w = w4[q], r = r4[q];
        acc += w.x * r.x + w.y * r.y + w.z * r.z + w.w * r.w;
    }
    red[tid] = acc;
    __syncthreads();
    for (int off = C >> 1; off; off >>= 1) {
        if (tid < off) red[tid] = fmaxf(red[tid], red[tid + off]);
        __syncthreads();
    }
    float mx = red[0];
    __syncthreads();
    red[tid] = expf(acc - mx);
    __syncthreads();
    for (int off = C >> 1; off; off >>= 1) {
        if (tid < off) red[tid] += red[tid + off];
        __syncthreads();
    }
    float lse = mx + logf(red[0]);
    dst[(size_t)s * C + tid] = acc - lse;
}

// ---------------- launch ----------------
extern "C" void kernel_launch(void* const* d_in, const int* in_sizes, int n_in,
                              void* d_out, int out_size) {
    const int*   word_seq   = (const int*)  d_in[0];
    const int*   chars      = (const int*)  d_in[1];
    const int*   char_lens  = (const int*)  d_in[2];
    const int*   feat_seq   = (const int*)  d_in[3];
    const float* char_emb   = (const float*)d_in[4];
    const float* word_emb   = (const float*)d_in[5];
    const float* prefix_emb = (const float*)d_in[6];
    const float* Wih_c = (const float*)d_in[7];
    const float* Whh_c = (const float*)d_in[8];
    const float* bih_c = (const float*)d_in[9];
    const float* bhh_c = (const float*)d_in[10];
    const float* Wih_f = (const float*)d_in[11];
    const float* Whh_f = (const float*)d_in[12];
    const float* bih_f = (const float*)d_in[13];
    const float* bhh_f = (const float*)d_in[14];
    const float* Wih_b = (const float*)d_in[15];
    const float* Whh_b = (const float*)d_in[16];
    const float* bih_b = (const float*)d_in[17];
    const float* bhh_b = (const float*)d_in[18];
    const float* Wpos  = (const float*)d_in[19];
    const float* bpos  = (const float*)d_in[20];
    const float* Wner  = (const float*)d_in[21];
    const float* bner  = (const float*)d_in[22];
    float* out = (float*)d_out;

    float *p_hA, *p_hB;
    __nv_bfloat16 *p_xc16h, *p_xc16l, *p_h16hA, *p_h16lA, *p_h16hB, *p_h16lB;
    cudaGetSymbolAddress((void**)&p_hA,  g_hA);
    cudaGetSymbolAddress((void**)&p_hB,  g_hB);
    cudaGetSymbolAddress((void**)&p_xc16h, g_xc16h);
    cudaGetSymbolAddress((void**)&p_xc16l, g_xc16l);
    cudaGetSymbolAddress((void**)&p_h16hA, g_h16hA);
    cudaGetSymbolAddress((void**)&p_h16lA, g_h16lA);
    cudaGetSymbolAddress((void**)&p_h16hB, g_h16hB);
    cudaGetSymbolAddress((void**)&p_h16lB, g_h16lB);

    cudaFuncSetAttribute(k_char_mma, cudaFuncAttributeMaxDynamicSharedMemorySize,
                         CSMEM_ALLOC);
    cudaFuncSetAttribute(k_xg_mma, cudaFuncAttributeMaxDynamicSharedMemorySize,
                         SMEM_XG_BYTES);

    // prep: sort, char prep, xg prep, gather
    k_sort<<<1, 256>>>(char_lens);
    k_prep_all<<<5120 + 8 + 8192, 256>>>(Wih_c, Whh_c, bih_c, bhh_c,
                                         feat_seq, prefix_emb);
    k_prep_xg<<<8200, 256>>>(Wih_f, Wih_b, bih_f, bhh_f, bih_b, bhh_b);
    k_gather_xc<<<(L * S * 64) / 256, 256>>>(chars, char_emb);

    // char LSTM: 16 mma.sync steps (128x64 tiles, 2 CTAs/SM), ping-pong
    dim3 gridC(G4H / 64, S / 128);
    for (int t = 0; t < L; ++t) {
        __nv_bfloat16* hch = (t & 1) ? p_h16hB : p_h16hA;
        __nv_bfloat16* hcl = (t & 1) ? p_h16lB : p_h16lA;
        __nv_bfloat16* hnh = (t & 1) ? p_h16hA : p_h16hB;
        __nv_bfloat16* hnl = (t & 1) ? p_h16lA : p_h16lB;
        float*         hnf = (t & 1) ? p_hA    : p_hB;
        k_char_mma<<<gridC, 256, CSMEM_ALLOC>>>(
            p_xc16h + (size_t)t * S * EC, p_xc16l + (size_t)t * S * EC,
            hch, hcl, hnh, hnl, hnf, t);
    }

    // word LSTM input (bf16 hi/lo) + x-gate GEMM via HMMA (fwd+bwd)
    k_build_wc16<<<(S * 512) / 256, 256>>>(word_seq, word_emb);
    dim3 gridX(G4HH / 128, S / 128, 2);
    k_xg_mma<<<gridX, 256, SMEM_XG_BYTES>>>();

    // sequential bi-LSTM recurrence (2 clusters of 8 CTAs, fwd + bwd concurrent)
    k_word_lstm<<<16, 512>>>(Whh_f, Whh_b);

    // output heads
    k_logits<<<S, NPOS>>>(Wpos, bpos, out, NPOS);
    k_logits<<<S, NNER>>>(Wner, bner, out + (size_t)S * NPOS, NNER);

    (void)in_sizes; (void)n_in; (void)out_size;
}